// round 8
// baseline (speedup 1.0000x reference)
#include <cuda_runtime.h>
#include <cuda_bf16.h>
#include <cstdint>

#define NCHUNK 20
#define TMR    64
#define THREADS 256
#define A_HL   9216             // bytes per A image (64 rows x 144B)
#define A_BUF  (2 * A_HL)       // hi + lo
#define OF_A   0
#define OF_X   (2 * A_BUF)                  // 36864
#define SMEM_TOTAL (OF_X + TMR * 132 * 4)   // 70656

// B fragments: [c][kt][nt][lane] = uint4(b0_hi, b1_hi, b0_lo, b1_lo)
__device__ __align__(16) uint4 g_Bf[NCHUNK * 4 * 8 * 32];

__device__ __forceinline__ uint32_t smem_u32(const void* p) {
    uint32_t a;
    asm("{ .reg .u64 t; cvta.to.shared.u64 t, %1; cvt.u32.u64 %0, t; }" : "=r"(a) : "l"(p));
    return a;
}
#define LDM_X4(r0, r1, r2, r3, addr) \
    asm volatile("ldmatrix.sync.aligned.m8n8.x4.shared.b16 {%0,%1,%2,%3}, [%4];" \
                 : "=r"(r0), "=r"(r1), "=r"(r2), "=r"(r3) : "r"(addr))
#define MMA16816(c, a0, a1, a2, a3, b0, b1) \
    asm volatile("mma.sync.aligned.m16n8k16.row.col.f32.bf16.bf16.f32 " \
                 "{%0,%1,%2,%3}, {%4,%5,%6,%7}, {%8,%9}, {%0,%1,%2,%3};" \
                 : "+f"((c)[0]), "+f"((c)[1]), "+f"((c)[2]), "+f"((c)[3]) \
                 : "r"(a0), "r"(a1), "r"(a2), "r"(a3), "r"(b0), "r"(b1))

__device__ __forceinline__ uint32_t pkbf2(float lo, float hi) {
    uint32_t d;
    asm("cvt.rn.bf16x2.f32 %0, %1, %2;" : "=r"(d) : "f"(hi), "f"(lo));
    return d;
}
__device__ __forceinline__ void bsplit(float v, unsigned short& h, unsigned short& l) {
    __nv_bfloat16 bh = __float2bfloat16(v);
    h = __bfloat16_as_ushort(bh);
    l = __bfloat16_as_ushort(__float2bfloat16(v - __bfloat162float(bh)));
}
__device__ __forceinline__ float wval(int c, int k, int n,
                                      const float* W1, const float* coef,
                                      const float* sb, const float* sp,
                                      const float* mask) {
    if (c < 16) {
        int i = c * 8 + (k >> 3), j = k & 7, io = i * 64 + n;
        return coef[io * 8 + j] * sp[io] * mask[io];
    }
    if (c < 18) {
        int io = ((c - 16) * 64 + k) * 64 + n;
        return sb[io] * mask[io];
    }
    return W1[n * 128 + (c - 18) * 64 + k];
}

__global__ void prepB_kernel(const float* __restrict__ W1, const float* __restrict__ coef,
                             const float* __restrict__ sb, const float* __restrict__ sp,
                             const float* __restrict__ mask) {
    int idx = blockIdx.x * blockDim.x + threadIdx.x;
    if (idx >= NCHUNK * 4 * 8 * 32) return;
    int lane = idx & 31, nt = (idx >> 5) & 7, kt = (idx >> 8) & 3, c = idx >> 10;
    int n  = nt * 8 + (lane >> 2);
    int k0 = kt * 16 + (lane & 3) * 2;
    float v00 = wval(c, k0,     n, W1, coef, sb, sp, mask);
    float v01 = wval(c, k0 + 1, n, W1, coef, sb, sp, mask);
    float v10 = wval(c, k0 + 8, n, W1, coef, sb, sp, mask);
    float v11 = wval(c, k0 + 9, n, W1, coef, sb, sp, mask);
    unsigned short h00, l00, h01, l01, h10, l10, h11, l11;
    bsplit(v00, h00, l00); bsplit(v01, h01, l01);
    bsplit(v10, h10, l10); bsplit(v11, h11, l11);
    uint4 r;
    r.x = (unsigned)h00 | ((unsigned)h01 << 16);
    r.y = (unsigned)h10 | ((unsigned)h11 << 16);
    r.z = (unsigned)l00 | ((unsigned)l01 << 16);
    r.w = (unsigned)l10 | ((unsigned)l11 << 16);
    g_Bf[idx] = r;
}

// ---- A-prep for chunk cc into buffer nb (all 256 threads, 64 rows) ----
__device__ __forceinline__ void prepA(int cc, int nb, int t, char* smA, const float* sX,
                                      float g0, float invh) {
    char* bAh = smA + nb * A_BUF;
    char* bAl = bAh + A_HL;
    if (cc < 16) {
        const int i0 = cc * 8, fl = t & 7;
#pragma unroll
        for (int e = 0; e < 2; ++e) {
            const int row = (t >> 3) + e * 32;
            float a  = sX[row * 132 + i0 + fl];
            float tt = (a - g0) * invh;
            float mf = floorf(tt);
            float u  = tt - mf;
            float u2 = u * u, u3 = u2 * u, omu = 1.0f - u;
            float w0 = (1.0f / 6.0f) * omu * omu * omu;
            float w1 = (1.0f / 6.0f) * (3.0f * u3 - 6.0f * u2 + 4.0f);
            float w2 = (1.0f / 6.0f) * (-3.0f * u3 + 3.0f * u2 + 3.0f * u + 1.0f);
            float w3 = (1.0f / 6.0f) * u3;
            int m = (tt >= 0.0f && mf <= 10.0f) ? (int)mf : 1000;
            int d = m - 3, p = d & 1, js = (d & ~1) >> 1;
            float a0 = p ? 0.f : w0, b0 = p ? w0 : w1;
            float a1 = p ? w1 : w2, b1 = p ? w2 : w3;
            uint32_t W0 = pkbf2(a0, b0), W1 = pkbf2(a1, b1), W2 = pkbf2(w3, 0.f);
            float r0l = a0 - __uint_as_float(W0 << 16);
            float r0h = b0 - __uint_as_float(W0 & 0xffff0000u);
            float r1l = a1 - __uint_as_float(W1 << 16);
            float r1h = b1 - __uint_as_float(W1 & 0xffff0000u);
            float r2l = w3 - __uint_as_float(W2 << 16);
            uint32_t L0 = pkbf2(r0l, r0h), L1 = pkbf2(r1l, r1h), L2 = pkbf2(r2l, 0.f);
            if (!p) { W2 = 0u; L2 = 0u; }
            uint32_t H[4], L[4];
#pragma unroll
            for (int jp = 0; jp < 4; ++jp) {
                int sel = jp - js;
                H[jp] = (sel == 0) ? W0 : (sel == 1) ? W1 : (sel == 2) ? W2 : 0u;
                L[jp] = (sel == 0) ? L0 : (sel == 1) ? L1 : (sel == 2) ? L2 : 0u;
            }
            *(uint4*)(bAh + row * 144 + fl * 16) = make_uint4(H[0], H[1], H[2], H[3]);
            *(uint4*)(bAl + row * 144 + fl * 16) = make_uint4(L[0], L[1], L[2], L[3]);
        }
    } else {
        const bool dosilu = (cc < 18);
        const int i0 = (cc & 1) * 64, row = t >> 2, f0 = (t & 3) * 16;
        float vv[16];
#pragma unroll
        for (int q = 0; q < 4; ++q) {
            float4 v = *(const float4*)(sX + row * 132 + i0 + f0 + q * 4);
            vv[q * 4 + 0] = v.x; vv[q * 4 + 1] = v.y; vv[q * 4 + 2] = v.z; vv[q * 4 + 3] = v.w;
        }
        uint32_t hq[8], lq[8];
#pragma unroll
        for (int q = 0; q < 8; ++q) {
            float pa = vv[2 * q], pb = vv[2 * q + 1];
            if (dosilu) {
                pa = pa / (1.0f + __expf(-pa));
                pb = pb / (1.0f + __expf(-pb));
            }
            hq[q] = pkbf2(pa, pb);
            float ra = pa - __uint_as_float(hq[q] << 16);
            float rb = pb - __uint_as_float(hq[q] & 0xffff0000u);
            lq[q] = pkbf2(ra, rb);
        }
        char* dH = bAh + row * 144 + f0 * 2;
        char* dL = bAl + row * 144 + f0 * 2;
        *(uint4*)(dH)      = make_uint4(hq[0], hq[1], hq[2], hq[3]);
        *(uint4*)(dH + 16) = make_uint4(hq[4], hq[5], hq[6], hq[7]);
        *(uint4*)(dL)      = make_uint4(lq[0], lq[1], lq[2], lq[3]);
        *(uint4*)(dL + 16) = make_uint4(lq[4], lq[5], lq[6], lq[7]);
    }
}

__global__ __launch_bounds__(THREADS, 2)
void enc_mma_kernel(const float* __restrict__ x, const float* __restrict__ gridp,
                    float* __restrict__ zout, float* __restrict__ xlout, int N) {
    extern __shared__ char sm[];
    char*  smA = sm + OF_A;
    float* sX  = (float*)(sm + OF_X);

    const int t = threadIdx.x, wid = t >> 5, lane = t & 31;
    const int wr = wid & 3, wc = wid >> 2;
    const int n0 = blockIdx.x * TMR;

    const float g0   = gridp[0];
    const float invh = 1.0f / (gridp[1] - gridp[0]);

    for (int p = t; p < TMR * 32; p += THREADS) {
        int row = p >> 5, c4 = (p & 31) << 2;
        int gn = n0 + row; if (gn >= N) gn = N - 1;
        *(float4*)(sX + row * 132 + c4) = *(const float4*)(x + (size_t)gn * 128 + c4);
    }

    float accz[4][4], accx[4][4];
#pragma unroll
    for (int a = 0; a < 4; a++)
#pragma unroll
        for (int b = 0; b < 4; b++) { accz[a][b] = 0.f; accx[a][b] = 0.f; }

    const int lrow = wr * 16 + (lane & 7) + ((lane >> 3) & 1) * 8;
    const uint32_t aOff = smem_u32(smA) + lrow * 144 + ((lane >> 4) * 8) * 2;

    // per-warp B fragment base (global, stays in L1)
    const uint4* gWB = g_Bf + (wc * 4) * 32 + lane;

    __syncthreads();   // sX ready

    prepA(0, 0, t, smA, sX, g0, invh);
    __syncthreads();

    for (int c = 0; c < NCHUNK; ++c) {
        const int cb = c & 1, nb = cb ^ 1;
        const bool more = (c + 1 < NCHUNK);
        const uint32_t aH = aOff + cb * A_BUF;
        const uint4* gB = gWB + c * 1024;

        uint4 Bf[2][4];
#pragma unroll
        for (int nt = 0; nt < 4; ++nt) Bf[0][nt] = gB[nt * 32];

#pragma unroll
        for (int kt = 0; kt < 4; ++kt) {
            uint32_t ah0, ah1, ah2, ah3, al0, al1, al2, al3;
            LDM_X4(ah0, ah1, ah2, ah3, aH + kt * 32);
            LDM_X4(al0, al1, al2, al3, aH + A_HL + kt * 32);
            if (kt < 3) {
#pragma unroll
                for (int nt = 0; nt < 4; ++nt)
                    Bf[(kt + 1) & 1][nt] = gB[((kt + 1) * 8 + nt) * 32];
            }
            const uint4* B = Bf[kt & 1];
            if (c < 18) {
#pragma unroll
                for (int nt = 0; nt < 4; ++nt) {
                    MMA16816(accz[nt], ah0, ah1, ah2, ah3, B[nt].x, B[nt].y);
                    MMA16816(accz[nt], ah0, ah1, ah2, ah3, B[nt].z, B[nt].w);
                    MMA16816(accz[nt], al0, al1, al2, al3, B[nt].x, B[nt].y);
                }
            } else {
#pragma unroll
                for (int nt = 0; nt < 4; ++nt) {
                    MMA16816(accx[nt], ah0, ah1, ah2, ah3, B[nt].x, B[nt].y);
                    MMA16816(accx[nt], ah0, ah1, ah2, ah3, B[nt].z, B[nt].w);
                    MMA16816(accx[nt], al0, al1, al2, al3, B[nt].x, B[nt].y);
                }
            }
        }
        if (more) prepA(c + 1, nb, t, smA, sX, g0, invh);
        __syncthreads();
    }

    // ---- epilogue ----
    float p0 = 0.f, p1 = 0.f;
#pragma unroll
    for (int nt = 0; nt < 4; ++nt) {
        p0 += accz[nt][0] * accz[nt][0] + accz[nt][1] * accz[nt][1];
        p1 += accz[nt][2] * accz[nt][2] + accz[nt][3] * accz[nt][3];
    }
    p0 += __shfl_xor_sync(0xffffffffu, p0, 1);
    p0 += __shfl_xor_sync(0xffffffffu, p0, 2);
    p1 += __shfl_xor_sync(0xffffffffu, p1, 1);
    p1 += __shfl_xor_sync(0xffffffffu, p1, 2);

    float* spart = sX;   // reuse: [coltile][row]
    const int r0 = wr * 16 + (lane >> 2), r1 = r0 + 8;
    if ((lane & 3) == 0) {
        spart[wc * TMR + r0] = p0;
        spart[wc * TMR + r1] = p1;
    }
    __syncthreads();

    const float fac0 = 0.8f / fmaxf(sqrtf(spart[r0] + spart[TMR + r0]), 1e-12f);
    const float fac1 = 0.8f / fmaxf(sqrtf(spart[r1] + spart[TMR + r1]), 1e-12f);
    const bool ok0 = (n0 + r0 < N), ok1 = (n0 + r1 < N);
#pragma unroll
    for (int nt = 0; nt < 4; ++nt) {
        int n = wc * 32 + nt * 8 + (lane & 3) * 2;
        if (ok0) {
            *(float2*)(zout  + (size_t)(n0 + r0) * 64 + n) = make_float2(accz[nt][0] * fac0, accz[nt][1] * fac0);
            *(float2*)(xlout + (size_t)(n0 + r0) * 64 + n) = make_float2(accx[nt][0], accx[nt][1]);
        }
        if (ok1) {
            *(float2*)(zout  + (size_t)(n0 + r1) * 64 + n) = make_float2(accz[nt][2] * fac1, accz[nt][3] * fac1);
            *(float2*)(xlout + (size_t)(n0 + r1) * 64 + n) = make_float2(accx[nt][2], accx[nt][3]);
        }
    }
}

extern "C" void kernel_launch(void* const* d_in, const int* in_sizes, int n_in,
                              void* d_out, int out_size) {
    const float* x          = (const float*)d_in[0];
    const float* W1         = (const float*)d_in[1];
    const float* grid       = (const float*)d_in[2];
    const float* coef       = (const float*)d_in[3];
    const float* scale_base = (const float*)d_in[4];
    const float* scale_sp   = (const float*)d_in[5];
    const float* mask       = (const float*)d_in[6];
    // d_in[7] = edge_index: unused by the reference

    const int N = in_sizes[0] / 128;
    float* out   = (float*)d_out;
    float* zout  = out;
    float* xlout = out + (size_t)N * 64;

    cudaFuncSetAttribute(enc_mma_kernel, cudaFuncAttributeMaxDynamicSharedMemorySize, SMEM_TOTAL);
    prepB_kernel<<<(NCHUNK * 4 * 8 * 32 + 255) / 256, 256>>>(W1, coef, scale_base, scale_sp, mask);
    enc_mma_kernel<<<(N + TMR - 1) / TMR, THREADS, SMEM_TOTAL>>>(x, grid, zout, xlout, N);
}

// round 9
// speedup vs baseline: 1.0715x; 1.0715x over previous
#include <cuda_runtime.h>
#include <cuda_bf16.h>
#include <cstdint>

#define NCHUNK 20
#define TMR    64
#define THREADS 256
#define A_HL   9216             // bytes per A image (64 rows x 144B)
#define A_BUF  (2 * A_HL)       // hi + lo
#define OF_A   0
#define OF_B   (2 * A_BUF)                  // 36864
#define OF_X   (OF_B + 2 * 16384)           // 69632
#define SMEM_TOTAL (OF_X + TMR * 132 * 4)   // 103424

// B fragments: [c][kt][nt][lane] = uint4(b0_hi, b1_hi, b0_lo, b1_lo)
__device__ __align__(16) uint4 g_Bf[NCHUNK * 4 * 8 * 32];

__device__ __forceinline__ uint32_t smem_u32(const void* p) {
    uint32_t a;
    asm("{ .reg .u64 t; cvta.to.shared.u64 t, %1; cvt.u32.u64 %0, t; }" : "=r"(a) : "l"(p));
    return a;
}
#define LDM_X4(r0, r1, r2, r3, addr) \
    asm volatile("ldmatrix.sync.aligned.m8n8.x4.shared.b16 {%0,%1,%2,%3}, [%4];" \
                 : "=r"(r0), "=r"(r1), "=r"(r2), "=r"(r3) : "r"(addr))
#define MMA16816(c, a0, a1, a2, a3, b0, b1) \
    asm volatile("mma.sync.aligned.m16n8k16.row.col.f32.bf16.bf16.f32 " \
                 "{%0,%1,%2,%3}, {%4,%5,%6,%7}, {%8,%9}, {%0,%1,%2,%3};" \
                 : "+f"((c)[0]), "+f"((c)[1]), "+f"((c)[2]), "+f"((c)[3]) \
                 : "r"(a0), "r"(a1), "r"(a2), "r"(a3), "r"(b0), "r"(b1))

__device__ __forceinline__ uint32_t pkbf2(float lo, float hi) {
    uint32_t d;
    asm("cvt.rn.bf16x2.f32 %0, %1, %2;" : "=r"(d) : "f"(hi), "f"(lo));
    return d;
}
__device__ __forceinline__ void bsplit(float v, unsigned short& h, unsigned short& l) {
    __nv_bfloat16 bh = __float2bfloat16(v);
    h = __bfloat16_as_ushort(bh);
    l = __bfloat16_as_ushort(__float2bfloat16(v - __bfloat162float(bh)));
}
__device__ __forceinline__ float wval(int c, int k, int n,
                                      const float* W1, const float* coef,
                                      const float* sb, const float* sp,
                                      const float* mask) {
    if (c < 16) {
        int i = c * 8 + (k >> 3), j = k & 7, io = i * 64 + n;
        return coef[io * 8 + j] * sp[io] * mask[io];
    }
    if (c < 18) {
        int io = ((c - 16) * 64 + k) * 64 + n;
        return sb[io] * mask[io];
    }
    return W1[n * 128 + (c - 18) * 64 + k];
}

__global__ void prepB_kernel(const float* __restrict__ W1, const float* __restrict__ coef,
                             const float* __restrict__ sb, const float* __restrict__ sp,
                             const float* __restrict__ mask) {
    int idx = blockIdx.x * blockDim.x + threadIdx.x;
    if (idx >= NCHUNK * 4 * 8 * 32) return;
    int lane = idx & 31, nt = (idx >> 5) & 7, kt = (idx >> 8) & 3, c = idx >> 10;
    int n  = nt * 8 + (lane >> 2);
    int k0 = kt * 16 + (lane & 3) * 2;
    float v00 = wval(c, k0,     n, W1, coef, sb, sp, mask);
    float v01 = wval(c, k0 + 1, n, W1, coef, sb, sp, mask);
    float v10 = wval(c, k0 + 8, n, W1, coef, sb, sp, mask);
    float v11 = wval(c, k0 + 9, n, W1, coef, sb, sp, mask);
    unsigned short h00, l00, h01, l01, h10, l10, h11, l11;
    bsplit(v00, h00, l00); bsplit(v01, h01, l01);
    bsplit(v10, h10, l10); bsplit(v11, h11, l11);
    uint4 r;
    r.x = (unsigned)h00 | ((unsigned)h01 << 16);
    r.y = (unsigned)h10 | ((unsigned)h11 << 16);
    r.z = (unsigned)l00 | ((unsigned)l01 << 16);
    r.w = (unsigned)l10 | ((unsigned)l11 << 16);
    g_Bf[idx] = r;
}

// ---- A-prep for chunk cc into buffer nb (select-based, 2 STS.128/eval) ----
__device__ __forceinline__ void prepA(int cc, int nb, int t, char* smA, const float* sX,
                                      float g0, float invh) {
    char* bAh = smA + nb * A_BUF;
    char* bAl = bAh + A_HL;
    if (cc < 16) {
        const int i0 = cc * 8, fl = t & 7;
#pragma unroll
        for (int e = 0; e < 2; ++e) {
            const int row = (t >> 3) + e * 32;
            float a  = sX[row * 132 + i0 + fl];
            float tt = (a - g0) * invh;
            float mf = floorf(tt);
            float u  = tt - mf;
            float u2 = u * u, u3 = u2 * u, omu = 1.0f - u;
            float w0 = (1.0f / 6.0f) * omu * omu * omu;
            float w1 = (1.0f / 6.0f) * (3.0f * u3 - 6.0f * u2 + 4.0f);
            float w2 = (1.0f / 6.0f) * (-3.0f * u3 + 3.0f * u2 + 3.0f * u + 1.0f);
            float w3 = (1.0f / 6.0f) * u3;
            int m = (tt >= 0.0f && mf <= 10.0f) ? (int)mf : 1000;
            int d = m - 3, p = d & 1, js = (d & ~1) >> 1;
            float a0 = p ? 0.f : w0, b0 = p ? w0 : w1;
            float a1 = p ? w1 : w2, b1 = p ? w2 : w3;
            uint32_t W0 = pkbf2(a0, b0), W1 = pkbf2(a1, b1), W2 = pkbf2(w3, 0.f);
            float r0l = a0 - __uint_as_float(W0 << 16);
            float r0h = b0 - __uint_as_float(W0 & 0xffff0000u);
            float r1l = a1 - __uint_as_float(W1 << 16);
            float r1h = b1 - __uint_as_float(W1 & 0xffff0000u);
            float r2l = w3 - __uint_as_float(W2 << 16);
            uint32_t L0 = pkbf2(r0l, r0h), L1 = pkbf2(r1l, r1h), L2 = pkbf2(r2l, 0.f);
            if (!p) { W2 = 0u; L2 = 0u; }
            uint32_t H[4], L[4];
#pragma unroll
            for (int jp = 0; jp < 4; ++jp) {
                int sel = jp - js;
                H[jp] = (sel == 0) ? W0 : (sel == 1) ? W1 : (sel == 2) ? W2 : 0u;
                L[jp] = (sel == 0) ? L0 : (sel == 1) ? L1 : (sel == 2) ? L2 : 0u;
            }
            *(uint4*)(bAh + row * 144 + fl * 16) = make_uint4(H[0], H[1], H[2], H[3]);
            *(uint4*)(bAl + row * 144 + fl * 16) = make_uint4(L[0], L[1], L[2], L[3]);
        }
    } else {
        const bool dosilu = (cc < 18);
        const int i0 = (cc & 1) * 64, row = t >> 2, f0 = (t & 3) * 16;
        float vv[16];
#pragma unroll
        for (int q = 0; q < 4; ++q) {
            float4 v = *(const float4*)(sX + row * 132 + i0 + f0 + q * 4);
            vv[q * 4 + 0] = v.x; vv[q * 4 + 1] = v.y; vv[q * 4 + 2] = v.z; vv[q * 4 + 3] = v.w;
        }
        uint32_t hq[8], lq[8];
#pragma unroll
        for (int q = 0; q < 8; ++q) {
            float pa = vv[2 * q], pb = vv[2 * q + 1];
            if (dosilu) {
                pa = pa / (1.0f + __expf(-pa));
                pb = pb / (1.0f + __expf(-pb));
            }
            hq[q] = pkbf2(pa, pb);
            float ra = pa - __uint_as_float(hq[q] << 16);
            float rb = pb - __uint_as_float(hq[q] & 0xffff0000u);
            lq[q] = pkbf2(ra, rb);
        }
        char* dH = bAh + row * 144 + f0 * 2;
        char* dL = bAl + row * 144 + f0 * 2;
        *(uint4*)(dH)      = make_uint4(hq[0], hq[1], hq[2], hq[3]);
        *(uint4*)(dH + 16) = make_uint4(hq[4], hq[5], hq[6], hq[7]);
        *(uint4*)(dL)      = make_uint4(lq[0], lq[1], lq[2], lq[3]);
        *(uint4*)(dL + 16) = make_uint4(lq[4], lq[5], lq[6], lq[7]);
    }
}

__global__ __launch_bounds__(THREADS, 2)
void enc_mma_kernel(const float* __restrict__ x, const float* __restrict__ gridp,
                    float* __restrict__ zout, float* __restrict__ xlout, int N) {
    extern __shared__ char sm[];
    char*  smA = sm + OF_A;
    uint4* sB  = (uint4*)(sm + OF_B);
    float* sX  = (float*)(sm + OF_X);

    const int t = threadIdx.x, wid = t >> 5, lane = t & 31;
    const int wr = wid & 3, wc = wid >> 2;
    const int n0 = blockIdx.x * TMR;

    const float g0   = gridp[0];
    const float invh = 1.0f / (gridp[1] - gridp[0]);

    for (int p = t; p < TMR * 32; p += THREADS) {
        int row = p >> 5, c4 = (p & 31) << 2;
        int gn = n0 + row; if (gn >= N) gn = N - 1;
        *(float4*)(sX + row * 132 + c4) = *(const float4*)(x + (size_t)gn * 128 + c4);
    }

    float accz[4][4], accx[4][4];
#pragma unroll
    for (int a = 0; a < 4; a++)
#pragma unroll
        for (int b = 0; b < 4; b++) { accz[a][b] = 0.f; accx[a][b] = 0.f; }

    const int lrow = wr * 16 + (lane & 7) + ((lane >> 3) & 1) * 8;
    const uint32_t aOff = smem_u32(smA) + lrow * 144 + ((lane >> 4) * 8) * 2;

    __syncthreads();   // sX ready

    // prologue: stage B(0), prep A(0) into buf 0
#pragma unroll
    for (int q = 0; q < 4; ++q) sB[t + q * 256] = g_Bf[t + q * 256];
    prepA(0, 0, t, smA, sX, g0, invh);
    __syncthreads();

    for (int c = 0; c < NCHUNK; ++c) {
        const int cb = c & 1, nb = cb ^ 1;
        const bool more = (c + 1 < NCHUNK);
        uint4 pb[4];
        if (more) {
#pragma unroll
            for (int q = 0; q < 4; ++q) pb[q] = g_Bf[(c + 1) * 1024 + t + q * 256];
        }
        // ---- consume chunk c ----
        const uint32_t aH = aOff + cb * A_BUF;
        const uint4* sBb = sB + cb * 1024;
#pragma unroll
        for (int kt = 0; kt < 4; ++kt) {
            uint32_t ah0, ah1, ah2, ah3, al0, al1, al2, al3;
            LDM_X4(ah0, ah1, ah2, ah3, aH + kt * 32);
            LDM_X4(al0, al1, al2, al3, aH + A_HL + kt * 32);
            if (c < 18) {
#pragma unroll
                for (int nt = 0; nt < 4; ++nt) {
                    uint4 B = sBb[(kt * 8 + wc * 4 + nt) * 32 + lane];
                    MMA16816(accz[nt], ah0, ah1, ah2, ah3, B.x, B.y);
                    MMA16816(accz[nt], ah0, ah1, ah2, ah3, B.z, B.w);
                    MMA16816(accz[nt], al0, al1, al2, al3, B.x, B.y);
                }
            } else {
#pragma unroll
                for (int nt = 0; nt < 4; ++nt) {
                    uint4 B = sBb[(kt * 8 + wc * 4 + nt) * 32 + lane];
                    MMA16816(accx[nt], ah0, ah1, ah2, ah3, B.x, B.y);
                    MMA16816(accx[nt], ah0, ah1, ah2, ah3, B.z, B.w);
                    MMA16816(accx[nt], al0, al1, al2, al3, B.x, B.y);
                }
            }
        }
        // ---- produce chunk c+1 ----
        if (more) {
#pragma unroll
            for (int q = 0; q < 4; ++q) sB[nb * 1024 + t + q * 256] = pb[q];
            prepA(c + 1, nb, t, smA, sX, g0, invh);
        }
        __syncthreads();
    }

    // ---- epilogue ----
    float p0 = 0.f, p1 = 0.f;
#pragma unroll
    for (int nt = 0; nt < 4; ++nt) {
        p0 += accz[nt][0] * accz[nt][0] + accz[nt][1] * accz[nt][1];
        p1 += accz[nt][2] * accz[nt][2] + accz[nt][3] * accz[nt][3];
    }
    p0 += __shfl_xor_sync(0xffffffffu, p0, 1);
    p0 += __shfl_xor_sync(0xffffffffu, p0, 2);
    p1 += __shfl_xor_sync(0xffffffffu, p1, 1);
    p1 += __shfl_xor_sync(0xffffffffu, p1, 2);

    float* spart = sX;   // reuse: [coltile][row]
    const int r0 = wr * 16 + (lane >> 2), r1 = r0 + 8;
    if ((lane & 3) == 0) {
        spart[wc * TMR + r0] = p0;
        spart[wc * TMR + r1] = p1;
    }
    __syncthreads();

    const float fac0 = 0.8f / fmaxf(sqrtf(spart[r0] + spart[TMR + r0]), 1e-12f);
    const float fac1 = 0.8f / fmaxf(sqrtf(spart[r1] + spart[TMR + r1]), 1e-12f);
    const bool ok0 = (n0 + r0 < N), ok1 = (n0 + r1 < N);
#pragma unroll
    for (int nt = 0; nt < 4; ++nt) {
        int n = wc * 32 + nt * 8 + (lane & 3) * 2;
        if (ok0) {
            *(float2*)(zout  + (size_t)(n0 + r0) * 64 + n) = make_float2(accz[nt][0] * fac0, accz[nt][1] * fac0);
            *(float2*)(xlout + (size_t)(n0 + r0) * 64 + n) = make_float2(accx[nt][0], accx[nt][1]);
        }
        if (ok1) {
            *(float2*)(zout  + (size_t)(n0 + r1) * 64 + n) = make_float2(accz[nt][2] * fac1, accz[nt][3] * fac1);
            *(float2*)(xlout + (size_t)(n0 + r1) * 64 + n) = make_float2(accx[nt][2], accx[nt][3]);
        }
    }
}

extern "C" void kernel_launch(void* const* d_in, const int* in_sizes, int n_in,
                              void* d_out, int out_size) {
    const float* x          = (const float*)d_in[0];
    const float* W1         = (const float*)d_in[1];
    const float* grid       = (const float*)d_in[2];
    const float* coef       = (const float*)d_in[3];
    const float* scale_base = (const float*)d_in[4];
    const float* scale_sp   = (const float*)d_in[5];
    const float* mask       = (const float*)d_in[6];
    // d_in[7] = edge_index: unused by the reference

    const int N = in_sizes[0] / 128;
    float* out   = (float*)d_out;
    float* zout  = out;
    float* xlout = out + (size_t)N * 64;

    cudaFuncSetAttribute(enc_mma_kernel, cudaFuncAttributeMaxDynamicSharedMemorySize, SMEM_TOTAL);
    prepB_kernel<<<(NCHUNK * 4 * 8 * 32 + 255) / 256, 256>>>(W1, coef, scale_base, scale_sp, mask);
    enc_mma_kernel<<<(N + TMR - 1) / TMR, THREADS, SMEM_TOTAL>>>(x, grid, zout, xlout, N);
}

// round 10
// speedup vs baseline: 1.3524x; 1.2622x over previous
#include <cuda_runtime.h>
#include <cuda_bf16.h>
#include <cstdint>

#define NCHUNK 20
#define TMR    128
#define THREADS 256
#define A_HL   18432            // bytes per A image (128 rows x 144B)
#define A_BUF  (2 * A_HL)       // hi + lo
#define OF_A   0
#define OF_B   (2 * A_BUF)                  // 73728
#define SMEM_TOTAL (OF_B + 2 * 16384)       // 106496

// B fragments: [c][kt][nt][lane] = uint4(b0_hi, b1_hi, b0_lo, b1_lo)
__device__ __align__(16) uint4 g_Bf[NCHUNK * 4 * 8 * 32];

__device__ __forceinline__ uint32_t smem_u32(const void* p) {
    uint32_t a;
    asm("{ .reg .u64 t; cvta.to.shared.u64 t, %1; cvt.u32.u64 %0, t; }" : "=r"(a) : "l"(p));
    return a;
}
#define LDM_X4(r0, r1, r2, r3, addr) \
    asm volatile("ldmatrix.sync.aligned.m8n8.x4.shared.b16 {%0,%1,%2,%3}, [%4];" \
                 : "=r"(r0), "=r"(r1), "=r"(r2), "=r"(r3) : "r"(addr))
#define MMA16816(c, a0, a1, a2, a3, b0, b1) \
    asm volatile("mma.sync.aligned.m16n8k16.row.col.f32.bf16.bf16.f32 " \
                 "{%0,%1,%2,%3}, {%4,%5,%6,%7}, {%8,%9}, {%0,%1,%2,%3};" \
                 : "+f"((c)[0]), "+f"((c)[1]), "+f"((c)[2]), "+f"((c)[3]) \
                 : "r"(a0), "r"(a1), "r"(a2), "r"(a3), "r"(b0), "r"(b1))
#define CP_ASYNC16(dst, src) \
    asm volatile("cp.async.ca.shared.global [%0], [%1], 16;" :: "r"(dst), "l"(src) : "memory")
#define CP_COMMIT() asm volatile("cp.async.commit_group;" ::: "memory")
#define CP_WAIT0()  asm volatile("cp.async.wait_group 0;" ::: "memory")

__device__ __forceinline__ uint32_t pkbf2(float lo, float hi) {
    uint32_t d;
    asm("cvt.rn.bf16x2.f32 %0, %1, %2;" : "=r"(d) : "f"(hi), "f"(lo));
    return d;
}
__device__ __forceinline__ void bsplit(float v, unsigned short& h, unsigned short& l) {
    __nv_bfloat16 bh = __float2bfloat16(v);
    h = __bfloat16_as_ushort(bh);
    l = __bfloat16_as_ushort(__float2bfloat16(v - __bfloat162float(bh)));
}
__device__ __forceinline__ float wval(int c, int k, int n,
                                      const float* W1, const float* coef,
                                      const float* sb, const float* sp,
                                      const float* mask) {
    if (c < 16) {
        int i = c * 8 + (k >> 3), j = k & 7, io = i * 64 + n;
        return coef[io * 8 + j] * sp[io] * mask[io];
    }
    if (c < 18) {
        int io = ((c - 16) * 64 + k) * 64 + n;
        return sb[io] * mask[io];
    }
    return W1[n * 128 + (c - 18) * 64 + k];
}

__global__ void prepB_kernel(const float* __restrict__ W1, const float* __restrict__ coef,
                             const float* __restrict__ sb, const float* __restrict__ sp,
                             const float* __restrict__ mask) {
    int idx = blockIdx.x * blockDim.x + threadIdx.x;
    if (idx >= NCHUNK * 4 * 8 * 32) return;
    int lane = idx & 31, nt = (idx >> 5) & 7, kt = (idx >> 8) & 3, c = idx >> 10;
    int n  = nt * 8 + (lane >> 2);
    int k0 = kt * 16 + (lane & 3) * 2;
    float v00 = wval(c, k0,     n, W1, coef, sb, sp, mask);
    float v01 = wval(c, k0 + 1, n, W1, coef, sb, sp, mask);
    float v10 = wval(c, k0 + 8, n, W1, coef, sb, sp, mask);
    float v11 = wval(c, k0 + 9, n, W1, coef, sb, sp, mask);
    unsigned short h00, l00, h01, l01, h10, l10, h11, l11;
    bsplit(v00, h00, l00); bsplit(v01, h01, l01);
    bsplit(v10, h10, l10); bsplit(v11, h11, l11);
    uint4 r;
    r.x = (unsigned)h00 | ((unsigned)h01 << 16);
    r.y = (unsigned)h10 | ((unsigned)h11 << 16);
    r.z = (unsigned)l00 | ((unsigned)l01 << 16);
    r.w = (unsigned)l10 | ((unsigned)l11 << 16);
    g_Bf[idx] = r;
}

// ---- A-prep for chunk cc into buffer nb (scatter-style, x from global) ----
__device__ __forceinline__ void prepA(int cc, int nb, int t, char* smA,
                                      const float* __restrict__ x,
                                      int n0, int N, float g0, float invh) {
    char* bAh = smA + nb * A_BUF;
    char* bAl = bAh + A_HL;
    if (cc < 16) {
        const int i0 = cc * 8, fl = t & 7;
        float av[4];
#pragma unroll
        for (int e = 0; e < 4; ++e) {
            int row = (t >> 3) + e * 32;
            int gn = n0 + row; if (gn >= N) gn = N - 1;
            av[e] = __ldg(x + (size_t)gn * 128 + i0 + fl);
        }
#pragma unroll
        for (int e = 0; e < 4; ++e) {
            const int row = (t >> 3) + e * 32;
            float a  = av[e];
            float tt = (a - g0) * invh;
            float mf = floorf(tt);
            float u  = tt - mf;
            float w0, w1, w2, w3; int m;
            if (tt >= 0.0f && mf <= 10.0f) {
                m = (int)mf;
                float u2 = u * u, u3 = u2 * u, omu = 1.0f - u;
                w0 = (1.0f / 6.0f) * omu * omu * omu;
                w1 = (1.0f / 6.0f) * (3.0f * u3 - 6.0f * u2 + 4.0f);
                w2 = (1.0f / 6.0f) * (-3.0f * u3 + 3.0f * u2 + 3.0f * u + 1.0f);
                w3 = (1.0f / 6.0f) * u3;
            } else { m = 100; w0 = w1 = w2 = w3 = 0.f; }
            char* dH = bAh + row * 144 + fl * 16;
            char* dL = bAl + row * 144 + fl * 16;
            *(uint4*)dH = make_uint4(0, 0, 0, 0);
            *(uint4*)dL = make_uint4(0, 0, 0, 0);
            int j0 = (m - 3) & ~1, p = (m - 3) & 1;
            float a0 = p ? 0.f : w0, b0 = p ? w0 : w1;
            float a1 = p ? w1 : w2, b1 = p ? w2 : w3;
            uint32_t W0 = pkbf2(a0, b0), W1 = pkbf2(a1, b1), W2 = pkbf2(w3, 0.f);
            float r0l = a0 - __uint_as_float(W0 << 16);
            float r0h = b0 - __uint_as_float(W0 & 0xffff0000u);
            float r1l = a1 - __uint_as_float(W1 << 16);
            float r1h = b1 - __uint_as_float(W1 & 0xffff0000u);
            float r2l = w3 - __uint_as_float(W2 << 16);
            uint32_t L0 = pkbf2(r0l, r0h), L1 = pkbf2(r1l, r1h), L2 = pkbf2(r2l, 0.f);
            if ((unsigned)j0 <= 6u)       { *(uint32_t*)(dH + j0 * 2) = W0;       *(uint32_t*)(dL + j0 * 2) = L0; }
            if ((unsigned)(j0 + 2) <= 6u) { *(uint32_t*)(dH + (j0 + 2) * 2) = W1; *(uint32_t*)(dL + (j0 + 2) * 2) = L1; }
            if (p && (unsigned)(j0 + 4) <= 6u) { *(uint32_t*)(dH + (j0 + 4) * 2) = W2; *(uint32_t*)(dL + (j0 + 4) * 2) = L2; }
        }
    } else {
        const bool dosilu = (cc < 18);
        const int i0 = (cc & 1) * 64, row = t >> 1, half = t & 1;
        int gn = n0 + row; if (gn >= N) gn = N - 1;
        const float4* xp = (const float4*)(x + (size_t)gn * 128 + i0 + half * 32);
        float vv[32];
#pragma unroll
        for (int q = 0; q < 8; ++q) {
            float4 v = __ldg(xp + q);
            vv[q * 4 + 0] = v.x; vv[q * 4 + 1] = v.y; vv[q * 4 + 2] = v.z; vv[q * 4 + 3] = v.w;
        }
        uint32_t hq[16], lq[16];
#pragma unroll
        for (int q = 0; q < 16; ++q) {
            float pa = vv[2 * q], pb = vv[2 * q + 1];
            if (dosilu) {
                pa = pa / (1.0f + __expf(-pa));
                pb = pb / (1.0f + __expf(-pb));
            }
            hq[q] = pkbf2(pa, pb);
            float ra = pa - __uint_as_float(hq[q] << 16);
            float rb = pb - __uint_as_float(hq[q] & 0xffff0000u);
            lq[q] = pkbf2(ra, rb);
        }
        char* dH = bAh + row * 144 + half * 64;
        char* dL = bAl + row * 144 + half * 64;
#pragma unroll
        for (int q = 0; q < 4; ++q) {
            *(uint4*)(dH + q * 16) = make_uint4(hq[q * 4 + 0], hq[q * 4 + 1], hq[q * 4 + 2], hq[q * 4 + 3]);
            *(uint4*)(dL + q * 16) = make_uint4(lq[q * 4 + 0], lq[q * 4 + 1], lq[q * 4 + 2], lq[q * 4 + 3]);
        }
    }
}

__global__ __launch_bounds__(THREADS, 2)
void enc_mma_kernel(const float* __restrict__ x, const float* __restrict__ gridp,
                    float* __restrict__ zout, float* __restrict__ xlout, int N) {
    extern __shared__ char sm[];
    char*  smA = sm + OF_A;
    uint4* sB  = (uint4*)(sm + OF_B);

    const int t = threadIdx.x, wid = t >> 5, lane = t & 31;
    const int wr = wid & 3, wc = wid >> 2;     // warp: rows wr*32..+31, cols wc*32..+31
    const int n0 = blockIdx.x * TMR;

    const float g0   = gridp[0];
    const float invh = 1.0f / (gridp[1] - gridp[0]);

    // acc[rt][nt][4]
    float accz[2][4][4], accx[2][4][4];
#pragma unroll
    for (int rt = 0; rt < 2; rt++)
#pragma unroll
        for (int nt = 0; nt < 4; nt++)
#pragma unroll
            for (int q = 0; q < 4; q++) { accz[rt][nt][q] = 0.f; accx[rt][nt][q] = 0.f; }

    const int lrow = wr * 32 + (lane & 7) + ((lane >> 3) & 1) * 8;
    const uint32_t aOff = smem_u32(smA) + lrow * 144 + ((lane >> 4) * 8) * 2;
    const uint32_t bSm  = smem_u32(sB);

    // prologue: cp.async B(0) -> buf0, prep A(0) -> buf0
    {
        uint32_t bdst = bSm + t * 16;
        const char* bsrc = (const char*)(g_Bf + t);
#pragma unroll
        for (int q = 0; q < 4; ++q) CP_ASYNC16(bdst + q * 4096, bsrc + (size_t)q * 4096);
        CP_COMMIT();
    }
    prepA(0, 0, t, smA, x, n0, N, g0, invh);
    CP_WAIT0();
    __syncthreads();

    for (int c = 0; c < NCHUNK; ++c) {
        const int cb = c & 1, nb = cb ^ 1;
        const bool more = (c + 1 < NCHUNK);
        if (more) {
            uint32_t bdst = bSm + nb * 16384 + t * 16;
            const char* bsrc = (const char*)(g_Bf + (c + 1) * 1024 + t);
#pragma unroll
            for (int q = 0; q < 4; ++q) CP_ASYNC16(bdst + q * 4096, bsrc + (size_t)q * 4096);
            CP_COMMIT();
        }
        // ---- consume chunk c ----
        const uint32_t aH = aOff + cb * A_BUF;
        const uint4* sBb = sB + cb * 1024;
#pragma unroll
        for (int kt = 0; kt < 4; ++kt) {
            uint4 B[4];
#pragma unroll
            for (int nt = 0; nt < 4; ++nt) B[nt] = sBb[(kt * 8 + wc * 4 + nt) * 32 + lane];
#pragma unroll
            for (int rt = 0; rt < 2; ++rt) {
                uint32_t ah0, ah1, ah2, ah3, al0, al1, al2, al3;
                LDM_X4(ah0, ah1, ah2, ah3, aH + rt * (16 * 144) + kt * 32);
                LDM_X4(al0, al1, al2, al3, aH + A_HL + rt * (16 * 144) + kt * 32);
                if (c < 18) {
#pragma unroll
                    for (int nt = 0; nt < 4; ++nt) {
                        MMA16816(accz[rt][nt], ah0, ah1, ah2, ah3, B[nt].x, B[nt].y);
                        MMA16816(accz[rt][nt], ah0, ah1, ah2, ah3, B[nt].z, B[nt].w);
                        MMA16816(accz[rt][nt], al0, al1, al2, al3, B[nt].x, B[nt].y);
                    }
                } else {
#pragma unroll
                    for (int nt = 0; nt < 4; ++nt) {
                        MMA16816(accx[rt][nt], ah0, ah1, ah2, ah3, B[nt].x, B[nt].y);
                        MMA16816(accx[rt][nt], ah0, ah1, ah2, ah3, B[nt].z, B[nt].w);
                        MMA16816(accx[rt][nt], al0, al1, al2, al3, B[nt].x, B[nt].y);
                    }
                }
            }
        }
        // ---- produce chunk c+1 ----
        if (more) prepA(c + 1, nb, t, smA, x, n0, N, g0, invh);
        CP_WAIT0();
        __syncthreads();
    }

    // ---- epilogue: row norms across the 2 col groups via smem ----
    float* spart = (float*)sm;   // reuse A region: [coltile][row] 2x128
#pragma unroll
    for (int rt = 0; rt < 2; ++rt) {
        float p0 = 0.f, p1 = 0.f;
#pragma unroll
        for (int nt = 0; nt < 4; ++nt) {
            p0 += accz[rt][nt][0] * accz[rt][nt][0] + accz[rt][nt][1] * accz[rt][nt][1];
            p1 += accz[rt][nt][2] * accz[rt][nt][2] + accz[rt][nt][3] * accz[rt][nt][3];
        }
        p0 += __shfl_xor_sync(0xffffffffu, p0, 1);
        p0 += __shfl_xor_sync(0xffffffffu, p0, 2);
        p1 += __shfl_xor_sync(0xffffffffu, p1, 1);
        p1 += __shfl_xor_sync(0xffffffffu, p1, 2);
        if ((lane & 3) == 0) {
            int r0 = wr * 32 + rt * 16 + (lane >> 2);
            spart[wc * TMR + r0]     = p0;
            spart[wc * TMR + r0 + 8] = p1;
        }
    }
    __syncthreads();

#pragma unroll
    for (int rt = 0; rt < 2; ++rt) {
        const int r0 = wr * 32 + rt * 16 + (lane >> 2), r1 = r0 + 8;
        const float fac0 = 0.8f / fmaxf(sqrtf(spart[r0] + spart[TMR + r0]), 1e-12f);
        const float fac1 = 0.8f / fmaxf(sqrtf(spart[r1] + spart[TMR + r1]), 1e-12f);
        const bool ok0 = (n0 + r0 < N), ok1 = (n0 + r1 < N);
#pragma unroll
        for (int nt = 0; nt < 4; ++nt) {
            int n = wc * 32 + nt * 8 + (lane & 3) * 2;
            if (ok0) {
                *(float2*)(zout  + (size_t)(n0 + r0) * 64 + n) = make_float2(accz[rt][nt][0] * fac0, accz[rt][nt][1] * fac0);
                *(float2*)(xlout + (size_t)(n0 + r0) * 64 + n) = make_float2(accx[rt][nt][0], accx[rt][nt][1]);
            }
            if (ok1) {
                *(float2*)(zout  + (size_t)(n0 + r1) * 64 + n) = make_float2(accz[rt][nt][2] * fac1, accz[rt][nt][3] * fac1);
                *(float2*)(xlout + (size_t)(n0 + r1) * 64 + n) = make_float2(accx[rt][nt][2], accx[rt][nt][3]);
            }
        }
    }
}

extern "C" void kernel_launch(void* const* d_in, const int* in_sizes, int n_in,
                              void* d_out, int out_size) {
    const float* x          = (const float*)d_in[0];
    const float* W1         = (const float*)d_in[1];
    const float* grid       = (const float*)d_in[2];
    const float* coef       = (const float*)d_in[3];
    const float* scale_base = (const float*)d_in[4];
    const float* scale_sp   = (const float*)d_in[5];
    const float* mask       = (const float*)d_in[6];
    // d_in[7] = edge_index: unused by the reference

    const int N = in_sizes[0] / 128;
    float* out   = (float*)d_out;
    float* zout  = out;
    float* xlout = out + (size_t)N * 64;

    cudaFuncSetAttribute(enc_mma_kernel, cudaFuncAttributeMaxDynamicSharedMemorySize, SMEM_TOTAL);
    prepB_kernel<<<(NCHUNK * 4 * 8 * 32 + 255) / 256, 256>>>(W1, coef, scale_base, scale_sp, mask);
    enc_mma_kernel<<<(N + TMR - 1) / TMR, THREADS, SMEM_TOTAL>>>(x, grid, zout, xlout, N);
}

// round 11
// speedup vs baseline: 1.8204x; 1.3461x over previous
#include <cuda_runtime.h>
#include <cuda_bf16.h>
#include <cstdint>

#define NCHUNK 20
#define TMR    128
#define THREADS 256
#define A_HL   18432            // bytes per A image (128 rows x 144B)
#define A_BUF  (2 * A_HL)       // hi + lo (spline chunks use hi only)
#define OF_A   0
#define OF_B   (2 * A_BUF)                  // 73728
#define SMEM_TOTAL (OF_B + 2 * 16384)       // 106496

// Spline B fragments (bf16 single): [c][kt][nt][lane] = uint2(b0, b1)
__device__ __align__(16) uint2 g_Bs[16 * 4 * 8 * 32];
// Dense-chunk B fragments (hi/lo): [c-16][kt][nt][lane] = uint4(b0h, b1h, b0l, b1l)
__device__ __align__(16) uint4 g_Bd[4 * 4 * 8 * 32];

__device__ __forceinline__ uint32_t smem_u32(const void* p) {
    uint32_t a;
    asm("{ .reg .u64 t; cvta.to.shared.u64 t, %1; cvt.u32.u64 %0, t; }" : "=r"(a) : "l"(p));
    return a;
}
#define LDM_X4(r0, r1, r2, r3, addr) \
    asm volatile("ldmatrix.sync.aligned.m8n8.x4.shared.b16 {%0,%1,%2,%3}, [%4];" \
                 : "=r"(r0), "=r"(r1), "=r"(r2), "=r"(r3) : "r"(addr))
#define MMA16816(c, a0, a1, a2, a3, b0, b1) \
    asm volatile("mma.sync.aligned.m16n8k16.row.col.f32.bf16.bf16.f32 " \
                 "{%0,%1,%2,%3}, {%4,%5,%6,%7}, {%8,%9}, {%0,%1,%2,%3};" \
                 : "+f"((c)[0]), "+f"((c)[1]), "+f"((c)[2]), "+f"((c)[3]) \
                 : "r"(a0), "r"(a1), "r"(a2), "r"(a3), "r"(b0), "r"(b1))
#define CP_ASYNC16(dst, src) \
    asm volatile("cp.async.ca.shared.global [%0], [%1], 16;" :: "r"(dst), "l"(src) : "memory")
#define CP_COMMIT() asm volatile("cp.async.commit_group;" ::: "memory")
#define CP_WAIT0()  asm volatile("cp.async.wait_group 0;" ::: "memory")

__device__ __forceinline__ uint32_t pkbf2(float lo, float hi) {
    uint32_t d;
    asm("cvt.rn.bf16x2.f32 %0, %1, %2;" : "=r"(d) : "f"(hi), "f"(lo));
    return d;
}
__device__ __forceinline__ void bsplit(float v, unsigned short& h, unsigned short& l) {
    __nv_bfloat16 bh = __float2bfloat16(v);
    h = __bfloat16_as_ushort(bh);
    l = __bfloat16_as_ushort(__float2bfloat16(v - __bfloat162float(bh)));
}
__device__ __forceinline__ float wval(int c, int k, int n,
                                      const float* W1, const float* coef,
                                      const float* sb, const float* sp,
                                      const float* mask) {
    if (c < 16) {
        int i = c * 8 + (k >> 3), j = k & 7, io = i * 64 + n;
        return coef[io * 8 + j] * sp[io] * mask[io];
    }
    if (c < 18) {
        int io = ((c - 16) * 64 + k) * 64 + n;
        return sb[io] * mask[io];
    }
    return W1[n * 128 + (c - 18) * 64 + k];
}

__global__ void prepB_kernel(const float* __restrict__ W1, const float* __restrict__ coef,
                             const float* __restrict__ sb, const float* __restrict__ sp,
                             const float* __restrict__ mask) {
    int idx = blockIdx.x * blockDim.x + threadIdx.x;
    if (idx >= NCHUNK * 4 * 8 * 32) return;
    int lane = idx & 31, nt = (idx >> 5) & 7, kt = (idx >> 8) & 3, c = idx >> 10;
    int n  = nt * 8 + (lane >> 2);
    int k0 = kt * 16 + (lane & 3) * 2;
    float v00 = wval(c, k0,     n, W1, coef, sb, sp, mask);
    float v01 = wval(c, k0 + 1, n, W1, coef, sb, sp, mask);
    float v10 = wval(c, k0 + 8, n, W1, coef, sb, sp, mask);
    float v11 = wval(c, k0 + 9, n, W1, coef, sb, sp, mask);
    if (c < 16) {
        uint2 r;
        r.x = pkbf2(v00, v01);
        r.y = pkbf2(v10, v11);
        g_Bs[idx] = r;
    } else {
        unsigned short h00, l00, h01, l01, h10, l10, h11, l11;
        bsplit(v00, h00, l00); bsplit(v01, h01, l01);
        bsplit(v10, h10, l10); bsplit(v11, h11, l11);
        uint4 r;
        r.x = (unsigned)h00 | ((unsigned)h01 << 16);
        r.y = (unsigned)h10 | ((unsigned)h11 << 16);
        r.z = (unsigned)l00 | ((unsigned)l01 << 16);
        r.w = (unsigned)l10 | ((unsigned)l11 << 16);
        g_Bd[idx - 16 * 1024] = r;
    }
}

// ---- A-prep for chunk cc into buffer nb ----
__device__ __forceinline__ void prepA(int cc, int nb, int t, char* smA,
                                      const float* __restrict__ x,
                                      int n0, int N, float g0, float invh) {
    char* bAh = smA + nb * A_BUF;
    char* bAl = bAh + A_HL;
    if (cc < 16) {
        // spline: single bf16 image (hi only), scatter-style
        const int i0 = cc * 8, fl = t & 7;
        float av[4];
#pragma unroll
        for (int e = 0; e < 4; ++e) {
            int row = (t >> 3) + e * 32;
            int gn = n0 + row; if (gn >= N) gn = N - 1;
            av[e] = __ldg(x + (size_t)gn * 128 + i0 + fl);
        }
#pragma unroll
        for (int e = 0; e < 4; ++e) {
            const int row = (t >> 3) + e * 32;
            float a  = av[e];
            float tt = (a - g0) * invh;
            float mf = floorf(tt);
            float u  = tt - mf;
            float w0, w1, w2, w3; int m;
            if (tt >= 0.0f && mf <= 10.0f) {
                m = (int)mf;
                float u2 = u * u, u3 = u2 * u, omu = 1.0f - u;
                w0 = (1.0f / 6.0f) * omu * omu * omu;
                w1 = (1.0f / 6.0f) * (3.0f * u3 - 6.0f * u2 + 4.0f);
                w2 = (1.0f / 6.0f) * (-3.0f * u3 + 3.0f * u2 + 3.0f * u + 1.0f);
                w3 = (1.0f / 6.0f) * u3;
            } else { m = 100; w0 = w1 = w2 = w3 = 0.f; }
            char* dH = bAh + row * 144 + fl * 16;
            *(uint4*)dH = make_uint4(0, 0, 0, 0);
            int j0 = (m - 3) & ~1, p = (m - 3) & 1;
            float a0 = p ? 0.f : w0, b0 = p ? w0 : w1;
            float a1 = p ? w1 : w2, b1 = p ? w2 : w3;
            uint32_t W0 = pkbf2(a0, b0), W1 = pkbf2(a1, b1), W2 = pkbf2(w3, 0.f);
            if ((unsigned)j0 <= 6u)       *(uint32_t*)(dH + j0 * 2) = W0;
            if ((unsigned)(j0 + 2) <= 6u) *(uint32_t*)(dH + (j0 + 2) * 2) = W1;
            if (p && (unsigned)(j0 + 4) <= 6u) *(uint32_t*)(dH + (j0 + 4) * 2) = W2;
        }
    } else {
        // dense (silu / x_lin): hi+lo bf16 images
        const bool dosilu = (cc < 18);
        const int i0 = (cc & 1) * 64, row = t >> 1, half = t & 1;
        int gn = n0 + row; if (gn >= N) gn = N - 1;
        const float4* xp = (const float4*)(x + (size_t)gn * 128 + i0 + half * 32);
        float vv[32];
#pragma unroll
        for (int q = 0; q < 8; ++q) {
            float4 v = __ldg(xp + q);
            vv[q * 4 + 0] = v.x; vv[q * 4 + 1] = v.y; vv[q * 4 + 2] = v.z; vv[q * 4 + 3] = v.w;
        }
        uint32_t hq[16], lq[16];
#pragma unroll
        for (int q = 0; q < 16; ++q) {
            float pa = vv[2 * q], pb = vv[2 * q + 1];
            if (dosilu) {
                pa = pa / (1.0f + __expf(-pa));
                pb = pb / (1.0f + __expf(-pb));
            }
            hq[q] = pkbf2(pa, pb);
            float ra = pa - __uint_as_float(hq[q] << 16);
            float rb = pb - __uint_as_float(hq[q] & 0xffff0000u);
            lq[q] = pkbf2(ra, rb);
        }
        char* dH = bAh + row * 144 + half * 64;
        char* dL = bAl + row * 144 + half * 64;
#pragma unroll
        for (int q = 0; q < 4; ++q) {
            *(uint4*)(dH + q * 16) = make_uint4(hq[q * 4 + 0], hq[q * 4 + 1], hq[q * 4 + 2], hq[q * 4 + 3]);
            *(uint4*)(dL + q * 16) = make_uint4(lq[q * 4 + 0], lq[q * 4 + 1], lq[q * 4 + 2], lq[q * 4 + 3]);
        }
    }
}

// ---- stage B for chunk cc into buffer nb via cp.async ----
__device__ __forceinline__ void stageB(int cc, int nb, int t, uint32_t bSm) {
    uint32_t bdst = bSm + nb * 16384 + t * 16;
    if (cc < 16) {
        const char* bsrc = (const char*)(g_Bs + cc * 1024) + t * 16;
#pragma unroll
        for (int q = 0; q < 2; ++q) CP_ASYNC16(bdst + q * 4096, bsrc + q * 4096);
    } else {
        const char* bsrc = (const char*)(g_Bd + (cc - 16) * 1024) + t * 16;
#pragma unroll
        for (int q = 0; q < 4; ++q) CP_ASYNC16(bdst + q * 4096, bsrc + q * 4096);
    }
    CP_COMMIT();
}

__global__ __launch_bounds__(THREADS, 2)
void enc_mma_kernel(const float* __restrict__ x, const float* __restrict__ gridp,
                    float* __restrict__ zout, float* __restrict__ xlout, int N) {
    extern __shared__ char sm[];
    char* smA = sm + OF_A;

    const int t = threadIdx.x, wid = t >> 5, lane = t & 31;
    const int wr = wid & 3, wc = wid >> 2;     // warp: rows wr*32..+31, cols wc*32..+31
    const int n0 = blockIdx.x * TMR;

    const float g0   = gridp[0];
    const float invh = 1.0f / (gridp[1] - gridp[0]);

    float accz[2][4][4], accx[2][4][4];
#pragma unroll
    for (int rt = 0; rt < 2; rt++)
#pragma unroll
        for (int nt = 0; nt < 4; nt++)
#pragma unroll
            for (int q = 0; q < 4; q++) { accz[rt][nt][q] = 0.f; accx[rt][nt][q] = 0.f; }

    const int lrow = wr * 32 + (lane & 7) + ((lane >> 3) & 1) * 8;
    const uint32_t aOff = smem_u32(smA) + lrow * 144 + ((lane >> 4) * 8) * 2;
    const uint32_t bSm  = smem_u32(sm + OF_B);

    // prologue
    stageB(0, 0, t, bSm);
    prepA(0, 0, t, smA, x, n0, N, g0, invh);
    CP_WAIT0();
    __syncthreads();

    for (int c = 0; c < NCHUNK; ++c) {
        const int cb = c & 1, nb = cb ^ 1;
        const bool more = (c + 1 < NCHUNK);
        if (more) stageB(c + 1, nb, t, bSm);

        const uint32_t aH = aOff + cb * A_BUF;
        if (c < 16) {
            // spline: single image, 1 MMA per (rt,nt), uint2 B frags
            const uint2* sB2 = (const uint2*)(sm + OF_B + cb * 16384);
#pragma unroll
            for (int kt = 0; kt < 4; ++kt) {
                uint2 B[4];
#pragma unroll
                for (int nt = 0; nt < 4; ++nt) B[nt] = sB2[(kt * 8 + wc * 4 + nt) * 32 + lane];
#pragma unroll
                for (int rt = 0; rt < 2; ++rt) {
                    uint32_t ah0, ah1, ah2, ah3;
                    LDM_X4(ah0, ah1, ah2, ah3, aH + rt * (16 * 144) + kt * 32);
#pragma unroll
                    for (int nt = 0; nt < 4; ++nt)
                        MMA16816(accz[rt][nt], ah0, ah1, ah2, ah3, B[nt].x, B[nt].y);
                }
            }
        } else {
            // dense: hi/lo 3-MMA
            const uint4* sBb = (const uint4*)(sm + OF_B + cb * 16384);
#pragma unroll
            for (int kt = 0; kt < 4; ++kt) {
                uint4 B[4];
#pragma unroll
                for (int nt = 0; nt < 4; ++nt) B[nt] = sBb[(kt * 8 + wc * 4 + nt) * 32 + lane];
#pragma unroll
                for (int rt = 0; rt < 2; ++rt) {
                    uint32_t ah0, ah1, ah2, ah3, al0, al1, al2, al3;
                    LDM_X4(ah0, ah1, ah2, ah3, aH + rt * (16 * 144) + kt * 32);
                    LDM_X4(al0, al1, al2, al3, aH + A_HL + rt * (16 * 144) + kt * 32);
                    if (c < 18) {
#pragma unroll
                        for (int nt = 0; nt < 4; ++nt) {
                            MMA16816(accz[rt][nt], ah0, ah1, ah2, ah3, B[nt].x, B[nt].y);
                            MMA16816(accz[rt][nt], ah0, ah1, ah2, ah3, B[nt].z, B[nt].w);
                            MMA16816(accz[rt][nt], al0, al1, al2, al3, B[nt].x, B[nt].y);
                        }
                    } else {
#pragma unroll
                        for (int nt = 0; nt < 4; ++nt) {
                            MMA16816(accx[rt][nt], ah0, ah1, ah2, ah3, B[nt].x, B[nt].y);
                            MMA16816(accx[rt][nt], ah0, ah1, ah2, ah3, B[nt].z, B[nt].w);
                            MMA16816(accx[rt][nt], al0, al1, al2, al3, B[nt].x, B[nt].y);
                        }
                    }
                }
            }
        }
        if (more) prepA(c + 1, nb, t, smA, x, n0, N, g0, invh);
        CP_WAIT0();
        __syncthreads();
    }

    // ---- epilogue ----
    float* spart = (float*)sm;   // reuse A region: [coltile][row] 2x128
#pragma unroll
    for (int rt = 0; rt < 2; ++rt) {
        float p0 = 0.f, p1 = 0.f;
#pragma unroll
        for (int nt = 0; nt < 4; ++nt) {
            p0 += accz[rt][nt][0] * accz[rt][nt][0] + accz[rt][nt][1] * accz[rt][nt][1];
            p1 += accz[rt][nt][2] * accz[rt][nt][2] + accz[rt][nt][3] * accz[rt][nt][3];
        }
        p0 += __shfl_xor_sync(0xffffffffu, p0, 1);
        p0 += __shfl_xor_sync(0xffffffffu, p0, 2);
        p1 += __shfl_xor_sync(0xffffffffu, p1, 1);
        p1 += __shfl_xor_sync(0xffffffffu, p1, 2);
        if ((lane & 3) == 0) {
            int r0 = wr * 32 + rt * 16 + (lane >> 2);
            spart[wc * TMR + r0]     = p0;
            spart[wc * TMR + r0 + 8] = p1;
        }
    }
    __syncthreads();

#pragma unroll
    for (int rt = 0; rt < 2; ++rt) {
        const int r0 = wr * 32 + rt * 16 + (lane >> 2), r1 = r0 + 8;
        const float fac0 = 0.8f / fmaxf(sqrtf(spart[r0] + spart[TMR + r0]), 1e-12f);
        const float fac1 = 0.8f / fmaxf(sqrtf(spart[r1] + spart[TMR + r1]), 1e-12f);
        const bool ok0 = (n0 + r0 < N), ok1 = (n0 + r1 < N);
#pragma unroll
        for (int nt = 0; nt < 4; ++nt) {
            int n = wc * 32 + nt * 8 + (lane & 3) * 2;
            if (ok0) {
                *(float2*)(zout  + (size_t)(n0 + r0) * 64 + n) = make_float2(accz[rt][nt][0] * fac0, accz[rt][nt][1] * fac0);
                *(float2*)(xlout + (size_t)(n0 + r0) * 64 + n) = make_float2(accx[rt][nt][0], accx[rt][nt][1]);
            }
            if (ok1) {
                *(float2*)(zout  + (size_t)(n0 + r1) * 64 + n) = make_float2(accz[rt][nt][2] * fac1, accz[rt][nt][3] * fac1);
                *(float2*)(xlout + (size_t)(n0 + r1) * 64 + n) = make_float2(accx[rt][nt][2], accx[rt][nt][3]);
            }
        }
    }
}

extern "C" void kernel_launch(void* const* d_in, const int* in_sizes, int n_in,
                              void* d_out, int out_size) {
    const float* x          = (const float*)d_in[0];
    const float* W1         = (const float*)d_in[1];
    const float* grid       = (const float*)d_in[2];
    const float* coef       = (const float*)d_in[3];
    const float* scale_base = (const float*)d_in[4];
    const float* scale_sp   = (const float*)d_in[5];
    const float* mask       = (const float*)d_in[6];
    // d_in[7] = edge_index: unused by the reference

    const int N = in_sizes[0] / 128;
    float* out   = (float*)d_out;
    float* zout  = out;
    float* xlout = out + (size_t)N * 64;

    cudaFuncSetAttribute(enc_mma_kernel, cudaFuncAttributeMaxDynamicSharedMemorySize, SMEM_TOTAL);
    prepB_kernel<<<(NCHUNK * 4 * 8 * 32 + 255) / 256, 256>>>(W1, coef, scale_base, scale_sp, mask);
    enc_mma_kernel<<<(N + TMR - 1) / TMR, THREADS, SMEM_TOTAL>>>(x, grid, zout, xlout, N);
}

// round 12
// speedup vs baseline: 1.9700x; 1.0822x over previous
#include <cuda_runtime.h>
#include <cuda_bf16.h>
#include <cstdint>

#define NCHUNK 20
#define NIT    12               // 8 spline-pair iterations + 4 dense iterations
#define TMR    128
#define THREADS 256
#define A_HL   18432            // bytes per A image (128 rows x 144B)
#define A_BUF  (2 * A_HL)       // two slots: spline pair (even/odd) or dense (hi/lo)
#define OF_A   0
#define OF_B   (2 * A_BUF)                  // 73728
#define SMEM_TOTAL (OF_B + 2 * 16384)       // 106496

// Spline B fragments (bf16 single): [c][kt][nt][lane] = uint2(b0, b1)
__device__ __align__(16) uint2 g_Bs[16 * 4 * 8 * 32];
// Dense-chunk B fragments (hi/lo): [c-16][kt][nt][lane] = uint4(b0h, b1h, b0l, b1l)
__device__ __align__(16) uint4 g_Bd[4 * 4 * 8 * 32];

__device__ __forceinline__ uint32_t smem_u32(const void* p) {
    uint32_t a;
    asm("{ .reg .u64 t; cvta.to.shared.u64 t, %1; cvt.u32.u64 %0, t; }" : "=r"(a) : "l"(p));
    return a;
}
#define LDM_X4(r0, r1, r2, r3, addr) \
    asm volatile("ldmatrix.sync.aligned.m8n8.x4.shared.b16 {%0,%1,%2,%3}, [%4];" \
                 : "=r"(r0), "=r"(r1), "=r"(r2), "=r"(r3) : "r"(addr))
#define MMA16816(c, a0, a1, a2, a3, b0, b1) \
    asm volatile("mma.sync.aligned.m16n8k16.row.col.f32.bf16.bf16.f32 " \
                 "{%0,%1,%2,%3}, {%4,%5,%6,%7}, {%8,%9}, {%0,%1,%2,%3};" \
                 : "+f"((c)[0]), "+f"((c)[1]), "+f"((c)[2]), "+f"((c)[3]) \
                 : "r"(a0), "r"(a1), "r"(a2), "r"(a3), "r"(b0), "r"(b1))
#define CP_ASYNC16(dst, src) \
    asm volatile("cp.async.ca.shared.global [%0], [%1], 16;" :: "r"(dst), "l"(src) : "memory")
#define CP_COMMIT() asm volatile("cp.async.commit_group;" ::: "memory")
#define CP_WAIT0()  asm volatile("cp.async.wait_group 0;" ::: "memory")

__device__ __forceinline__ uint32_t pkbf2(float lo, float hi) {
    uint32_t d;
    asm("cvt.rn.bf16x2.f32 %0, %1, %2;" : "=r"(d) : "f"(hi), "f"(lo));
    return d;
}
__device__ __forceinline__ void bsplit(float v, unsigned short& h, unsigned short& l) {
    __nv_bfloat16 bh = __float2bfloat16(v);
    h = __bfloat16_as_ushort(bh);
    l = __bfloat16_as_ushort(__float2bfloat16(v - __bfloat162float(bh)));
}
__device__ __forceinline__ float wval(int c, int k, int n,
                                      const float* W1, const float* coef,
                                      const float* sb, const float* sp,
                                      const float* mask) {
    if (c < 16) {
        int i = c * 8 + (k >> 3), j = k & 7, io = i * 64 + n;
        return coef[io * 8 + j] * sp[io] * mask[io];
    }
    if (c < 18) {
        int io = ((c - 16) * 64 + k) * 64 + n;
        return sb[io] * mask[io];
    }
    return W1[n * 128 + (c - 18) * 64 + k];
}

__global__ void prepB_kernel(const float* __restrict__ W1, const float* __restrict__ coef,
                             const float* __restrict__ sb, const float* __restrict__ sp,
                             const float* __restrict__ mask) {
    int idx = blockIdx.x * blockDim.x + threadIdx.x;
    if (idx >= NCHUNK * 4 * 8 * 32) return;
    int lane = idx & 31, nt = (idx >> 5) & 7, kt = (idx >> 8) & 3, c = idx >> 10;
    int n  = nt * 8 + (lane >> 2);
    int k0 = kt * 16 + (lane & 3) * 2;
    float v00 = wval(c, k0,     n, W1, coef, sb, sp, mask);
    float v01 = wval(c, k0 + 1, n, W1, coef, sb, sp, mask);
    float v10 = wval(c, k0 + 8, n, W1, coef, sb, sp, mask);
    float v11 = wval(c, k0 + 9, n, W1, coef, sb, sp, mask);
    if (c < 16) {
        uint2 r;
        r.x = pkbf2(v00, v01);
        r.y = pkbf2(v10, v11);
        g_Bs[idx] = r;
    } else {
        unsigned short h00, l00, h01, l01, h10, l10, h11, l11;
        bsplit(v00, h00, l00); bsplit(v01, h01, l01);
        bsplit(v10, h10, l10); bsplit(v11, h11, l11);
        uint4 r;
        r.x = (unsigned)h00 | ((unsigned)h01 << 16);
        r.y = (unsigned)h10 | ((unsigned)h11 << 16);
        r.z = (unsigned)l00 | ((unsigned)l01 << 16);
        r.w = (unsigned)l10 | ((unsigned)l11 << 16);
        g_Bd[idx - 16 * 1024] = r;
    }
}

// ---- spline-pair A-prep: chunks c0, c0+1 into slots 0/1 of buffer nb ----
__device__ __forceinline__ void prepSplinePair(int c0, int nb, int t, char* smA,
                                               const float* __restrict__ x,
                                               int n0, int N, float g0, float invh) {
    const int fl = t & 7;
    float av[2][4];
#pragma unroll
    for (int sub = 0; sub < 2; ++sub) {
        const int i0 = (c0 + sub) * 8;
#pragma unroll
        for (int e = 0; e < 4; ++e) {
            int row = (t >> 3) + e * 32;
            int gn = n0 + row; if (gn >= N) gn = N - 1;
            av[sub][e] = __ldg(x + (size_t)gn * 128 + i0 + fl);
        }
    }
#pragma unroll
    for (int sub = 0; sub < 2; ++sub) {
        char* dst = smA + nb * A_BUF + sub * A_HL;
#pragma unroll
        for (int e = 0; e < 4; ++e) {
            const int row = (t >> 3) + e * 32;
            float a  = av[sub][e];
            float tt = (a - g0) * invh;
            float mf = floorf(tt);
            float u  = tt - mf;
            float w0, w1, w2, w3; int m;
            if (tt >= 0.0f && mf <= 10.0f) {
                m = (int)mf;
                float u2 = u * u, u3 = u2 * u, omu = 1.0f - u;
                w0 = (1.0f / 6.0f) * omu * omu * omu;
                w1 = (1.0f / 6.0f) * (3.0f * u3 - 6.0f * u2 + 4.0f);
                w2 = (1.0f / 6.0f) * (-3.0f * u3 + 3.0f * u2 + 3.0f * u + 1.0f);
                w3 = (1.0f / 6.0f) * u3;
            } else { m = 100; w0 = w1 = w2 = w3 = 0.f; }
            char* dH = dst + row * 144 + fl * 16;
            *(uint4*)dH = make_uint4(0, 0, 0, 0);
            int j0 = (m - 3) & ~1, p = (m - 3) & 1;
            float a0 = p ? 0.f : w0, b0 = p ? w0 : w1;
            float a1 = p ? w1 : w2, b1 = p ? w2 : w3;
            uint32_t W0 = pkbf2(a0, b0), W1 = pkbf2(a1, b1), W2 = pkbf2(w3, 0.f);
            if ((unsigned)j0 <= 6u)       *(uint32_t*)(dH + j0 * 2) = W0;
            if ((unsigned)(j0 + 2) <= 6u) *(uint32_t*)(dH + (j0 + 2) * 2) = W1;
            if (p && (unsigned)(j0 + 4) <= 6u) *(uint32_t*)(dH + (j0 + 4) * 2) = W2;
        }
    }
}

// ---- dense A-prep (silu / x_lin): hi slot 0, lo slot 1 ----
__device__ __forceinline__ void prepDense(int cc, int nb, int t, char* smA,
                                          const float* __restrict__ x,
                                          int n0, int N) {
    char* bAh = smA + nb * A_BUF;
    char* bAl = bAh + A_HL;
    const bool dosilu = (cc < 18);
    const int i0 = (cc & 1) * 64, row = t >> 1, half = t & 1;
    int gn = n0 + row; if (gn >= N) gn = N - 1;
    const float4* xp = (const float4*)(x + (size_t)gn * 128 + i0 + half * 32);
    float vv[32];
#pragma unroll
    for (int q = 0; q < 8; ++q) {
        float4 v = __ldg(xp + q);
        vv[q * 4 + 0] = v.x; vv[q * 4 + 1] = v.y; vv[q * 4 + 2] = v.z; vv[q * 4 + 3] = v.w;
    }
    uint32_t hq[16], lq[16];
#pragma unroll
    for (int q = 0; q < 16; ++q) {
        float pa = vv[2 * q], pb = vv[2 * q + 1];
        if (dosilu) {
            pa = pa / (1.0f + __expf(-pa));
            pb = pb / (1.0f + __expf(-pb));
        }
        hq[q] = pkbf2(pa, pb);
        float ra = pa - __uint_as_float(hq[q] << 16);
        float rb = pb - __uint_as_float(hq[q] & 0xffff0000u);
        lq[q] = pkbf2(ra, rb);
    }
    char* dH = bAh + row * 144 + half * 64;
    char* dL = bAl + row * 144 + half * 64;
#pragma unroll
    for (int q = 0; q < 4; ++q) {
        *(uint4*)(dH + q * 16) = make_uint4(hq[q * 4 + 0], hq[q * 4 + 1], hq[q * 4 + 2], hq[q * 4 + 3]);
        *(uint4*)(dL + q * 16) = make_uint4(lq[q * 4 + 0], lq[q * 4 + 1], lq[q * 4 + 2], lq[q * 4 + 3]);
    }
}

// ---- stage B for iteration 'it' into buffer nb (always 16KB) ----
__device__ __forceinline__ void stageB(int it, int nb, int t, uint32_t bSm) {
    uint32_t bdst = bSm + nb * 16384 + t * 16;
    const char* bsrc = (it < 8)
        ? (const char*)(g_Bs + it * 2048) + t * 16        // spline pair: chunks 2it, 2it+1
        : (const char*)(g_Bd + (it - 8) * 1024) + t * 16; // dense chunk 16 + (it-8)
#pragma unroll
    for (int q = 0; q < 4; ++q) CP_ASYNC16(bdst + q * 4096, bsrc + q * 4096);
    CP_COMMIT();
}

__device__ __forceinline__ void prepIt(int it, int nb, int t, char* smA,
                                       const float* __restrict__ x,
                                       int n0, int N, float g0, float invh) {
    if (it < 8) prepSplinePair(it * 2, nb, t, smA, x, n0, N, g0, invh);
    else        prepDense(it + 8, nb, t, smA, x, n0, N);
}

__global__ __launch_bounds__(THREADS, 2)
void enc_mma_kernel(const float* __restrict__ x, const float* __restrict__ gridp,
                    float* __restrict__ zout, float* __restrict__ xlout, int N) {
    extern __shared__ char sm[];
    char* smA = sm + OF_A;

    const int t = threadIdx.x, wid = t >> 5, lane = t & 31;
    const int wr = wid & 3, wc = wid >> 2;     // warp: rows wr*32..+31, cols wc*32..+31
    const int n0 = blockIdx.x * TMR;

    const float g0   = gridp[0];
    const float invh = 1.0f / (gridp[1] - gridp[0]);

    float accz[2][4][4], accx[2][4][4];
#pragma unroll
    for (int rt = 0; rt < 2; rt++)
#pragma unroll
        for (int nt = 0; nt < 4; nt++)
#pragma unroll
            for (int q = 0; q < 4; q++) { accz[rt][nt][q] = 0.f; accx[rt][nt][q] = 0.f; }

    const int lrow = wr * 32 + (lane & 7) + ((lane >> 3) & 1) * 8;
    const uint32_t aOff = smem_u32(smA) + lrow * 144 + ((lane >> 4) * 8) * 2;
    const uint32_t bSm  = smem_u32(sm + OF_B);

    // prologue
    stageB(0, 0, t, bSm);
    prepIt(0, 0, t, smA, x, n0, N, g0, invh);
    CP_WAIT0();
    __syncthreads();

    for (int it = 0; it < NIT; ++it) {
        const int cb = it & 1, nb = cb ^ 1;
        const bool more = (it + 1 < NIT);
        if (more) stageB(it + 1, nb, t, bSm);

        if (it < 8) {
            // spline pair: two single-bf16 sub-chunks, slots 0/1
#pragma unroll
            for (int h = 0; h < 2; ++h) {
                const uint2* sB2 = (const uint2*)(sm + OF_B + cb * 16384 + h * 8192);
                const uint32_t aH = aOff + cb * A_BUF + h * A_HL;
#pragma unroll
                for (int kt = 0; kt < 4; ++kt) {
                    uint2 B[4];
#pragma unroll
                    for (int nt = 0; nt < 4; ++nt) B[nt] = sB2[(kt * 8 + wc * 4 + nt) * 32 + lane];
#pragma unroll
                    for (int rt = 0; rt < 2; ++rt) {
                        uint32_t ah0, ah1, ah2, ah3;
                        LDM_X4(ah0, ah1, ah2, ah3, aH + rt * (16 * 144) + kt * 32);
#pragma unroll
                        for (int nt = 0; nt < 4; ++nt)
                            MMA16816(accz[rt][nt], ah0, ah1, ah2, ah3, B[nt].x, B[nt].y);
                    }
                }
            }
        } else {
            // dense: hi/lo 3-MMA
            const int cc = it + 8;
            const uint4* sBb = (const uint4*)(sm + OF_B + cb * 16384);
            const uint32_t aH = aOff + cb * A_BUF;
#pragma unroll
            for (int kt = 0; kt < 4; ++kt) {
                uint4 B[4];
#pragma unroll
                for (int nt = 0; nt < 4; ++nt) B[nt] = sBb[(kt * 8 + wc * 4 + nt) * 32 + lane];
#pragma unroll
                for (int rt = 0; rt < 2; ++rt) {
                    uint32_t ah0, ah1, ah2, ah3, al0, al1, al2, al3;
                    LDM_X4(ah0, ah1, ah2, ah3, aH + rt * (16 * 144) + kt * 32);
                    LDM_X4(al0, al1, al2, al3, aH + A_HL + rt * (16 * 144) + kt * 32);
                    if (cc < 18) {
#pragma unroll
                        for (int nt = 0; nt < 4; ++nt) {
                            MMA16816(accz[rt][nt], ah0, ah1, ah2, ah3, B[nt].x, B[nt].y);
                            MMA16816(accz[rt][nt], ah0, ah1, ah2, ah3, B[nt].z, B[nt].w);
                            MMA16816(accz[rt][nt], al0, al1, al2, al3, B[nt].x, B[nt].y);
                        }
                    } else {
#pragma unroll
                        for (int nt = 0; nt < 4; ++nt) {
                            MMA16816(accx[rt][nt], ah0, ah1, ah2, ah3, B[nt].x, B[nt].y);
                            MMA16816(accx[rt][nt], ah0, ah1, ah2, ah3, B[nt].z, B[nt].w);
                            MMA16816(accx[rt][nt], al0, al1, al2, al3, B[nt].x, B[nt].y);
                        }
                    }
                }
            }
        }
        if (more) prepIt(it + 1, nb, t, smA, x, n0, N, g0, invh);
        CP_WAIT0();
        __syncthreads();
    }

    // ---- epilogue ----
    float* spart = (float*)sm;   // reuse A region: [coltile][row] 2x128
#pragma unroll
    for (int rt = 0; rt < 2; ++rt) {
        float p0 = 0.f, p1 = 0.f;
#pragma unroll
        for (int nt = 0; nt < 4; ++nt) {
            p0 += accz[rt][nt][0] * accz[rt][nt][0] + accz[rt][nt][1] * accz[rt][nt][1];
            p1 += accz[rt][nt][2] * accz[rt][nt][2] + accz[rt][nt][3] * accz[rt][nt][3];
        }
        p0 += __shfl_xor_sync(0xffffffffu, p0, 1);
        p0 += __shfl_xor_sync(0xffffffffu, p0, 2);
        p1 += __shfl_xor_sync(0xffffffffu, p1, 1);
        p1 += __shfl_xor_sync(0xffffffffu, p1, 2);
        if ((lane & 3) == 0) {
            int r0 = wr * 32 + rt * 16 + (lane >> 2);
            spart[wc * TMR + r0]     = p0;
            spart[wc * TMR + r0 + 8] = p1;
        }
    }
    __syncthreads();

#pragma unroll
    for (int rt = 0; rt < 2; ++rt) {
        const int r0 = wr * 32 + rt * 16 + (lane >> 2), r1 = r0 + 8;
        const float fac0 = 0.8f / fmaxf(sqrtf(spart[r0] + spart[TMR + r0]), 1e-12f);
        const float fac1 = 0.8f / fmaxf(sqrtf(spart[r1] + spart[TMR + r1]), 1e-12f);
        const bool ok0 = (n0 + r0 < N), ok1 = (n0 + r1 < N);
#pragma unroll
        for (int nt = 0; nt < 4; ++nt) {
            int n = wc * 32 + nt * 8 + (lane & 3) * 2;
            if (ok0) {
                *(float2*)(zout  + (size_t)(n0 + r0) * 64 + n) = make_float2(accz[rt][nt][0] * fac0, accz[rt][nt][1] * fac0);
                *(float2*)(xlout + (size_t)(n0 + r0) * 64 + n) = make_float2(accx[rt][nt][0], accx[rt][nt][1]);
            }
            if (ok1) {
                *(float2*)(zout  + (size_t)(n0 + r1) * 64 + n) = make_float2(accz[rt][nt][2] * fac1, accz[rt][nt][3] * fac1);
                *(float2*)(xlout + (size_t)(n0 + r1) * 64 + n) = make_float2(accx[rt][nt][2], accx[rt][nt][3]);
            }
        }
    }
}

extern "C" void kernel_launch(void* const* d_in, const int* in_sizes, int n_in,
                              void* d_out, int out_size) {
    const float* x          = (const float*)d_in[0];
    const float* W1         = (const float*)d_in[1];
    const float* grid       = (const float*)d_in[2];
    const float* coef       = (const float*)d_in[3];
    const float* scale_base = (const float*)d_in[4];
    const float* scale_sp   = (const float*)d_in[5];
    const float* mask       = (const float*)d_in[6];
    // d_in[7] = edge_index: unused by the reference

    const int N = in_sizes[0] / 128;
    float* out   = (float*)d_out;
    float* zout  = out;
    float* xlout = out + (size_t)N * 64;

    cudaFuncSetAttribute(enc_mma_kernel, cudaFuncAttributeMaxDynamicSharedMemorySize, SMEM_TOTAL);
    prepB_kernel<<<(NCHUNK * 4 * 8 * 32 + 255) / 256, 256>>>(W1, coef, scale_base, scale_sp, mask);
    enc_mma_kernel<<<(N + TMR - 1) / TMR, THREADS, SMEM_TOTAL>>>(x, grid, zout, xlout, N);
}

// round 13
// speedup vs baseline: 2.1202x; 1.0762x over previous
#include <cuda_runtime.h>
#include <cuda_bf16.h>
#include <cstdint>

#define NCHUNK 20
#define NIT    11               // 8 spline pairs + 1 silu pair + 2 xlin dense
#define TMR    128
#define THREADS 256
#define A_HL   18432            // bytes per A image (128 rows x 144B)
#define A_BUF  (2 * A_HL)       // two slots
#define OF_A   0
#define OF_B   (2 * A_BUF)                  // 73728
#define SMEM_TOTAL (OF_B + 2 * 16384)       // 106496

// Single-bf16 B fragments (16 spline + 2 silu chunks): [c][kt][nt][lane] = uint2(b0, b1)
__device__ __align__(16) uint2 g_Bs[18 * 4 * 8 * 32];
// x_lin B fragments (hi/lo): [c-18][kt][nt][lane] = uint4(b0h, b1h, b0l, b1l)
__device__ __align__(16) uint4 g_Bd[2 * 4 * 8 * 32];

__device__ __forceinline__ uint32_t smem_u32(const void* p) {
    uint32_t a;
    asm("{ .reg .u64 t; cvta.to.shared.u64 t, %1; cvt.u32.u64 %0, t; }" : "=r"(a) : "l"(p));
    return a;
}
#define LDM_X4(r0, r1, r2, r3, addr) \
    asm volatile("ldmatrix.sync.aligned.m8n8.x4.shared.b16 {%0,%1,%2,%3}, [%4];" \
                 : "=r"(r0), "=r"(r1), "=r"(r2), "=r"(r3) : "r"(addr))
#define MMA16816(c, a0, a1, a2, a3, b0, b1) \
    asm volatile("mma.sync.aligned.m16n8k16.row.col.f32.bf16.bf16.f32 " \
                 "{%0,%1,%2,%3}, {%4,%5,%6,%7}, {%8,%9}, {%0,%1,%2,%3};" \
                 : "+f"((c)[0]), "+f"((c)[1]), "+f"((c)[2]), "+f"((c)[3]) \
                 : "r"(a0), "r"(a1), "r"(a2), "r"(a3), "r"(b0), "r"(b1))
#define CP_ASYNC16(dst, src) \
    asm volatile("cp.async.ca.shared.global [%0], [%1], 16;" :: "r"(dst), "l"(src) : "memory")
#define CP_COMMIT() asm volatile("cp.async.commit_group;" ::: "memory")
#define CP_WAIT0()  asm volatile("cp.async.wait_group 0;" ::: "memory")

__device__ __forceinline__ uint32_t pkbf2(float lo, float hi) {
    uint32_t d;
    asm("cvt.rn.bf16x2.f32 %0, %1, %2;" : "=r"(d) : "f"(hi), "f"(lo));
    return d;
}
__device__ __forceinline__ void bsplit(float v, unsigned short& h, unsigned short& l) {
    __nv_bfloat16 bh = __float2bfloat16(v);
    h = __bfloat16_as_ushort(bh);
    l = __bfloat16_as_ushort(__float2bfloat16(v - __bfloat162float(bh)));
}
__device__ __forceinline__ float wval(int c, int k, int n,
                                      const float* W1, const float* coef,
                                      const float* sb, const float* sp,
                                      const float* mask) {
    if (c < 16) {
        int i = c * 8 + (k >> 3), j = k & 7, io = i * 64 + n;
        return coef[io * 8 + j] * sp[io] * mask[io];
    }
    if (c < 18) {
        int io = ((c - 16) * 64 + k) * 64 + n;
        return sb[io] * mask[io];
    }
    return W1[n * 128 + (c - 18) * 64 + k];
}

__global__ void prepB_kernel(const float* __restrict__ W1, const float* __restrict__ coef,
                             const float* __restrict__ sb, const float* __restrict__ sp,
                             const float* __restrict__ mask) {
    int idx = blockIdx.x * blockDim.x + threadIdx.x;
    if (idx >= NCHUNK * 4 * 8 * 32) return;
    int lane = idx & 31, nt = (idx >> 5) & 7, kt = (idx >> 8) & 3, c = idx >> 10;
    int n  = nt * 8 + (lane >> 2);
    int k0 = kt * 16 + (lane & 3) * 2;
    float v00 = wval(c, k0,     n, W1, coef, sb, sp, mask);
    float v01 = wval(c, k0 + 1, n, W1, coef, sb, sp, mask);
    float v10 = wval(c, k0 + 8, n, W1, coef, sb, sp, mask);
    float v11 = wval(c, k0 + 9, n, W1, coef, sb, sp, mask);
    if (c < 18) {
        uint2 r;
        r.x = pkbf2(v00, v01);
        r.y = pkbf2(v10, v11);
        g_Bs[idx] = r;
    } else {
        unsigned short h00, l00, h01, l01, h10, l10, h11, l11;
        bsplit(v00, h00, l00); bsplit(v01, h01, l01);
        bsplit(v10, h10, l10); bsplit(v11, h11, l11);
        uint4 r;
        r.x = (unsigned)h00 | ((unsigned)h01 << 16);
        r.y = (unsigned)h10 | ((unsigned)h11 << 16);
        r.z = (unsigned)l00 | ((unsigned)l01 << 16);
        r.w = (unsigned)l10 | ((unsigned)l11 << 16);
        g_Bd[idx - 18 * 1024] = r;
    }
}

// ---- spline-pair A-prep: chunks c0, c0+1 into slots 0/1 of buffer nb ----
__device__ __forceinline__ void prepSplinePair(int c0, int nb, int t, char* smA,
                                               const float* __restrict__ x,
                                               int n0, int N, float g0, float invh) {
    const int fl = t & 7;
    float av[2][4];
#pragma unroll
    for (int sub = 0; sub < 2; ++sub) {
        const int i0 = (c0 + sub) * 8;
#pragma unroll
        for (int e = 0; e < 4; ++e) {
            int row = (t >> 3) + e * 32;
            int gn = n0 + row; if (gn >= N) gn = N - 1;
            av[sub][e] = __ldg(x + (size_t)gn * 128 + i0 + fl);
        }
    }
#pragma unroll
    for (int sub = 0; sub < 2; ++sub) {
        char* dst = smA + nb * A_BUF + sub * A_HL;
#pragma unroll
        for (int e = 0; e < 4; ++e) {
            const int row = (t >> 3) + e * 32;
            float a  = av[sub][e];
            float tt = (a - g0) * invh;
            float mf = floorf(tt);
            float u  = tt - mf;
            float w0, w1, w2, w3; int m;
            if (tt >= 0.0f && mf <= 10.0f) {
                m = (int)mf;
                float u2 = u * u, u3 = u2 * u, omu = 1.0f - u;
                w0 = (1.0f / 6.0f) * omu * omu * omu;
                w1 = (1.0f / 6.0f) * (3.0f * u3 - 6.0f * u2 + 4.0f);
                w2 = (1.0f / 6.0f) * (-3.0f * u3 + 3.0f * u2 + 3.0f * u + 1.0f);
                w3 = (1.0f / 6.0f) * u3;
            } else { m = 100; w0 = w1 = w2 = w3 = 0.f; }
            char* dH = dst + row * 144 + fl * 16;
            *(uint4*)dH = make_uint4(0, 0, 0, 0);
            int j0 = (m - 3) & ~1, p = (m - 3) & 1;
            float a0 = p ? 0.f : w0, b0 = p ? w0 : w1;
            float a1 = p ? w1 : w2, b1 = p ? w2 : w3;
            uint32_t W0 = pkbf2(a0, b0), W1 = pkbf2(a1, b1), W2 = pkbf2(w3, 0.f);
            if ((unsigned)j0 <= 6u)       *(uint32_t*)(dH + j0 * 2) = W0;
            if ((unsigned)(j0 + 2) <= 6u) *(uint32_t*)(dH + (j0 + 2) * 2) = W1;
            if (p && (unsigned)(j0 + 4) <= 6u) *(uint32_t*)(dH + (j0 + 4) * 2) = W2;
        }
    }
}

// ---- silu-pair A-prep: chunks 16,17 (feats 0..63 -> slot 0, 64..127 -> slot 1) ----
// single-bf16 image per sub-chunk; each thread: one row, one 64-feature half.
__device__ __forceinline__ void prepSiluPair(int nb, int t, char* smA,
                                             const float* __restrict__ x,
                                             int n0, int N) {
    const int row = t >> 1, half = t & 1;
    int gn = n0 + row; if (gn >= N) gn = N - 1;
    const float4* xp = (const float4*)(x + (size_t)gn * 128 + half * 64);
    char* dst = smA + nb * A_BUF + half * A_HL + row * 144;
#pragma unroll
    for (int pass = 0; pass < 2; ++pass) {
        float vv[32];
#pragma unroll
        for (int q = 0; q < 8; ++q) {
            float4 v = __ldg(xp + pass * 8 + q);
            vv[q * 4 + 0] = v.x; vv[q * 4 + 1] = v.y; vv[q * 4 + 2] = v.z; vv[q * 4 + 3] = v.w;
        }
        uint32_t hq[16];
#pragma unroll
        for (int q = 0; q < 16; ++q) {
            float pa = vv[2 * q], pb = vv[2 * q + 1];
            pa = pa / (1.0f + __expf(-pa));
            pb = pb / (1.0f + __expf(-pb));
            hq[q] = pkbf2(pa, pb);
        }
#pragma unroll
        for (int q = 0; q < 4; ++q)
            *(uint4*)(dst + pass * 64 + q * 16) =
                make_uint4(hq[q * 4 + 0], hq[q * 4 + 1], hq[q * 4 + 2], hq[q * 4 + 3]);
    }
}

// ---- x_lin dense A-prep: hi slot 0, lo slot 1 ----
__device__ __forceinline__ void prepDense(int cc, int nb, int t, char* smA,
                                          const float* __restrict__ x,
                                          int n0, int N) {
    char* bAh = smA + nb * A_BUF;
    char* bAl = bAh + A_HL;
    const int i0 = (cc & 1) * 64, row = t >> 1, half = t & 1;
    int gn = n0 + row; if (gn >= N) gn = N - 1;
    const float4* xp = (const float4*)(x + (size_t)gn * 128 + i0 + half * 32);
    float vv[32];
#pragma unroll
    for (int q = 0; q < 8; ++q) {
        float4 v = __ldg(xp + q);
        vv[q * 4 + 0] = v.x; vv[q * 4 + 1] = v.y; vv[q * 4 + 2] = v.z; vv[q * 4 + 3] = v.w;
    }
    uint32_t hq[16], lq[16];
#pragma unroll
    for (int q = 0; q < 16; ++q) {
        float pa = vv[2 * q], pb = vv[2 * q + 1];
        hq[q] = pkbf2(pa, pb);
        float ra = pa - __uint_as_float(hq[q] << 16);
        float rb = pb - __uint_as_float(hq[q] & 0xffff0000u);
        lq[q] = pkbf2(ra, rb);
    }
    char* dH = bAh + row * 144 + half * 64;
    char* dL = bAl + row * 144 + half * 64;
#pragma unroll
    for (int q = 0; q < 4; ++q) {
        *(uint4*)(dH + q * 16) = make_uint4(hq[q * 4 + 0], hq[q * 4 + 1], hq[q * 4 + 2], hq[q * 4 + 3]);
        *(uint4*)(dL + q * 16) = make_uint4(lq[q * 4 + 0], lq[q * 4 + 1], lq[q * 4 + 2], lq[q * 4 + 3]);
    }
}

// ---- stage B for iteration 'it' into buffer nb (16KB) ----
__device__ __forceinline__ void stageB(int it, int nb, int t, uint32_t bSm) {
    uint32_t bdst = bSm + nb * 16384 + t * 16;
    const char* bsrc = (it <= 8)
        ? (const char*)(g_Bs + it * 2048) + t * 16        // pair: chunks 2it, 2it+1
        : (const char*)(g_Bd + (it - 9) * 1024) + t * 16; // xlin chunk 18 + (it-9)
#pragma unroll
    for (int q = 0; q < 4; ++q) CP_ASYNC16(bdst + q * 4096, bsrc + q * 4096);
    CP_COMMIT();
}

__device__ __forceinline__ void prepIt(int it, int nb, int t, char* smA,
                                       const float* __restrict__ x,
                                       int n0, int N, float g0, float invh) {
    if (it < 8)       prepSplinePair(it * 2, nb, t, smA, x, n0, N, g0, invh);
    else if (it == 8) prepSiluPair(nb, t, smA, x, n0, N);
    else              prepDense(it + 9, nb, t, smA, x, n0, N);
}

__global__ __launch_bounds__(THREADS, 2)
void enc_mma_kernel(const float* __restrict__ x, const float* __restrict__ gridp,
                    float* __restrict__ zout, float* __restrict__ xlout, int N) {
    extern __shared__ char sm[];
    char* smA = sm + OF_A;

    const int t = threadIdx.x, wid = t >> 5, lane = t & 31;
    const int wr = wid & 3, wc = wid >> 2;     // warp: rows wr*32..+31, cols wc*32..+31
    const int n0 = blockIdx.x * TMR;

    const float g0   = gridp[0];
    const float invh = 1.0f / (gridp[1] - gridp[0]);

    float accz[2][4][4], accx[2][4][4];
#pragma unroll
    for (int rt = 0; rt < 2; rt++)
#pragma unroll
        for (int nt = 0; nt < 4; nt++)
#pragma unroll
            for (int q = 0; q < 4; q++) { accz[rt][nt][q] = 0.f; accx[rt][nt][q] = 0.f; }

    const int lrow = wr * 32 + (lane & 7) + ((lane >> 3) & 1) * 8;
    const uint32_t aOff = smem_u32(smA) + lrow * 144 + ((lane >> 4) * 8) * 2;
    const uint32_t bSm  = smem_u32(sm + OF_B);

    // prologue
    stageB(0, 0, t, bSm);
    prepIt(0, 0, t, smA, x, n0, N, g0, invh);
    CP_WAIT0();
    __syncthreads();

    for (int it = 0; it < NIT; ++it) {
        const int cb = it & 1, nb = cb ^ 1;
        const bool more = (it + 1 < NIT);
        if (more) stageB(it + 1, nb, t, bSm);

        if (it <= 8) {
            // pair iteration (spline or silu): two single-bf16 sub-chunks, slots 0/1
#pragma unroll
            for (int h = 0; h < 2; ++h) {
                const uint2* sB2 = (const uint2*)(sm + OF_B + cb * 16384 + h * 8192);
                const uint32_t aH = aOff + cb * A_BUF + h * A_HL;
#pragma unroll
                for (int kt = 0; kt < 4; ++kt) {
                    uint2 B[4];
#pragma unroll
                    for (int nt = 0; nt < 4; ++nt) B[nt] = sB2[(kt * 8 + wc * 4 + nt) * 32 + lane];
#pragma unroll
                    for (int rt = 0; rt < 2; ++rt) {
                        uint32_t ah0, ah1, ah2, ah3;
                        LDM_X4(ah0, ah1, ah2, ah3, aH + rt * (16 * 144) + kt * 32);
#pragma unroll
                        for (int nt = 0; nt < 4; ++nt)
                            MMA16816(accz[rt][nt], ah0, ah1, ah2, ah3, B[nt].x, B[nt].y);
                    }
                }
            }
        } else {
            // x_lin dense: hi/lo 3-MMA
            const uint4* sBb = (const uint4*)(sm + OF_B + cb * 16384);
            const uint32_t aH = aOff + cb * A_BUF;
#pragma unroll
            for (int kt = 0; kt < 4; ++kt) {
                uint4 B[4];
#pragma unroll
                for (int nt = 0; nt < 4; ++nt) B[nt] = sBb[(kt * 8 + wc * 4 + nt) * 32 + lane];
#pragma unroll
                for (int rt = 0; rt < 2; ++rt) {
                    uint32_t ah0, ah1, ah2, ah3, al0, al1, al2, al3;
                    LDM_X4(ah0, ah1, ah2, ah3, aH + rt * (16 * 144) + kt * 32);
                    LDM_X4(al0, al1, al2, al3, aH + A_HL + rt * (16 * 144) + kt * 32);
#pragma unroll
                    for (int nt = 0; nt < 4; ++nt) {
                        MMA16816(accx[rt][nt], ah0, ah1, ah2, ah3, B[nt].x, B[nt].y);
                        MMA16816(accx[rt][nt], ah0, ah1, ah2, ah3, B[nt].z, B[nt].w);
                        MMA16816(accx[rt][nt], al0, al1, al2, al3, B[nt].x, B[nt].y);
                    }
                }
            }
        }
        if (more) prepIt(it + 1, nb, t, smA, x, n0, N, g0, invh);
        CP_WAIT0();
        __syncthreads();
    }

    // ---- epilogue ----
    float* spart = (float*)sm;   // reuse A region: [coltile][row] 2x128
#pragma unroll
    for (int rt = 0; rt < 2; ++rt) {
        float p0 = 0.f, p1 = 0.f;
#pragma unroll
        for (int nt = 0; nt < 4; ++nt) {
            p0 += accz[rt][nt][0] * accz[rt][nt][0] + accz[rt][nt][1] * accz[rt][nt][1];
            p1 += accz[rt][nt][2] * accz[rt][nt][2] + accz[rt][nt][3] * accz[rt][nt][3];
        }
        p0 += __shfl_xor_sync(0xffffffffu, p0, 1);
        p0 += __shfl_xor_sync(0xffffffffu, p0, 2);
        p1 += __shfl_xor_sync(0xffffffffu, p1, 1);
        p1 += __shfl_xor_sync(0xffffffffu, p1, 2);
        if ((lane & 3) == 0) {
            int r0 = wr * 32 + rt * 16 + (lane >> 2);
            spart[wc * TMR + r0]     = p0;
            spart[wc * TMR + r0 + 8] = p1;
        }
    }
    __syncthreads();

#pragma unroll
    for (int rt = 0; rt < 2; ++rt) {
        const int r0 = wr * 32 + rt * 16 + (lane >> 2), r1 = r0 + 8;
        const float fac0 = 0.8f / fmaxf(sqrtf(spart[r0] + spart[TMR + r0]), 1e-12f);
        const float fac1 = 0.8f / fmaxf(sqrtf(spart[r1] + spart[TMR + r1]), 1e-12f);
        const bool ok0 = (n0 + r0 < N), ok1 = (n0 + r1 < N);
#pragma unroll
        for (int nt = 0; nt < 4; ++nt) {
            int n = wc * 32 + nt * 8 + (lane & 3) * 2;
            if (ok0) {
                *(float2*)(zout  + (size_t)(n0 + r0) * 64 + n) = make_float2(accz[rt][nt][0] * fac0, accz[rt][nt][1] * fac0);
                *(float2*)(xlout + (size_t)(n0 + r0) * 64 + n) = make_float2(accx[rt][nt][0], accx[rt][nt][1]);
            }
            if (ok1) {
                *(float2*)(zout  + (size_t)(n0 + r1) * 64 + n) = make_float2(accz[rt][nt][2] * fac1, accz[rt][nt][3] * fac1);
                *(float2*)(xlout + (size_t)(n0 + r1) * 64 + n) = make_float2(accx[rt][nt][2], accx[rt][nt][3]);
            }
        }
    }
}

extern "C" void kernel_launch(void* const* d_in, const int* in_sizes, int n_in,
                              void* d_out, int out_size) {
    const float* x          = (const float*)d_in[0];
    const float* W1         = (const float*)d_in[1];
    const float* grid       = (const float*)d_in[2];
    const float* coef       = (const float*)d_in[3];
    const float* scale_base = (const float*)d_in[4];
    const float* scale_sp   = (const float*)d_in[5];
    const float* mask       = (const float*)d_in[6];
    // d_in[7] = edge_index: unused by the reference

    const int N = in_sizes[0] / 128;
    float* out   = (float*)d_out;
    float* zout  = out;
    float* xlout = out + (size_t)N * 64;

    cudaFuncSetAttribute(enc_mma_kernel, cudaFuncAttributeMaxDynamicSharedMemorySize, SMEM_TOTAL);
    prepB_kernel<<<(NCHUNK * 4 * 8 * 32 + 255) / 256, 256>>>(W1, coef, scale_base, scale_sp, mask);
    enc_mma_kernel<<<(N + TMR - 1) / TMR, THREADS, SMEM_TOTAL>>>(x, grid, zout, xlout, N);
}